// round 5
// baseline (speedup 1.0000x reference)
#include <cuda_runtime.h>
#include <cstdint>

#define H64 64
#define EE_MAX 50000
#define NN_MAX 20000

// ---------------- scratch (static device globals) ---------------------------
__device__ float    g_ht0[EE_MAX * H64 + 256];
__device__ float    g_ht1[EE_MAX * H64 + 256];
__device__ uint32_t g_w2b0[65 * 2176];
__device__ uint32_t g_w2b1[130 * 2176];
__device__ float    g_agg0[NN_MAX * H64];
__device__ float    g_agg1[NN_MAX * H64];

// ---------------- PTX helpers ------------------------------------------------
__device__ __forceinline__ uint32_t smem_u32(const void* p) {
    return (uint32_t)__cvta_generic_to_shared(p);
}
__device__ __forceinline__ uint32_t tf32r(float f) {
    uint32_t u; asm("cvt.rna.tf32.f32 %0, %1;" : "=r"(u) : "f"(f)); return u;
}
__device__ __forceinline__ void cp_async16(uint32_t s, const void* g) {
    asm volatile("cp.async.cg.shared.global [%0], [%1], 16;" :: "r"(s), "l"(g));
}
#define CP_COMMIT() asm volatile("cp.async.commit_group;" ::: "memory")
#define CP_WAIT1()  asm volatile("cp.async.wait_group 1;" ::: "memory")

__device__ __forceinline__ void mma_tf32(float* d, uint32_t a0, uint32_t a1,
                                         uint32_t a2, uint32_t a3,
                                         uint32_t b0, uint32_t b1) {
    asm volatile(
        "mma.sync.aligned.m16n8k8.row.col.f32.tf32.tf32.f32 "
        "{%0,%1,%2,%3}, {%4,%5,%6,%7}, {%8,%9}, {%0,%1,%2,%3};"
        : "+f"(d[0]), "+f"(d[1]), "+f"(d[2]), "+f"(d[3])
        : "r"(a0), "r"(a1), "r"(a2), "r"(a3), "r"(b0), "r"(b1));
}

// ---------------- chunk->kap mapping (reordered for i-half locality) --------
// L0 (IN=32): c in [0,64): k=c, i=k_local       kap = c*32 + kl
//             c == 64   : bias, i = kl          kap = 2048 + kl
// L1 (IN=64): c in [0,64): k=c, i-half 0        kap = c*64 + kl
//             c == 64   : bias, i-half 0        kap = 4096 + kl
//             c in [65,129): k=c-65, i-half 1   kap = (c-65)*64 + 32 + kl
//             c == 129  : bias, i-half 1        kap = 4128 + kl
__host__ __device__ __forceinline__ int kap_of(int IN_C, int c, int kl) {
    if (IN_C == 32) return (c < 64) ? c * 32 + kl : 2048 + kl;
    if (c < 64)  return c * 64 + kl;
    if (c == 64) return 4096 + kl;
    if (c < 129) return (c - 65) * 64 + 32 + kl;
    return 4128 + kl;
}

// ---------------- kernel 1: both edge MLPs, h^T stored [j][e] ---------------
__global__ void edge_mlp_both_kernel(const float* __restrict__ ea,
                                     const float* __restrict__ w1_0,
                                     const float* __restrict__ b1_0,
                                     const float* __restrict__ w1_1,
                                     const float* __restrict__ b1_1,
                                     float* __restrict__ ht0,
                                     float* __restrict__ ht1, int E)
{
    int e = blockIdx.x * blockDim.x + threadIdx.x;
    int j = blockIdx.y;
    if (e >= E) return;
    float a0 = __ldg(&ea[2 * e]);
    float a1 = __ldg(&ea[2 * e + 1]);
    const float* w1 = blockIdx.z ? w1_1 : w1_0;
    const float* b1 = blockIdx.z ? b1_1 : b1_0;
    float* ht       = blockIdx.z ? ht1  : ht0;
    float v = fmaf(a0, __ldg(&w1[j]), fmaf(a1, __ldg(&w1[H64 + j]), __ldg(&b1[j])));
    ht[(size_t)j * E + e] = fmaxf(v, 0.0f);
}

// ---------------- kernel 2: pack both tf32 B tables (pair layout) -----------
// word offset in chunk: row*136 + n*2 + p ; row = s*4+t ; k_local = s*8+t+4p
__global__ void prep_both_kernel(const float* __restrict__ w2_0,
                                 const float* __restrict__ b2_0,
                                 const float* __restrict__ w2_1,
                                 const float* __restrict__ b2_1)
{
    int idx = blockIdx.x * blockDim.x + threadIdx.x;
    if (idx >= 130 * 2048) return;
    int c = idx >> 11, rem = idx & 2047;
    int n = rem & 63;
    int rowp = rem >> 6;
    int row = rowp >> 1, p = rowp & 1;
    int s = row >> 2, t = row & 3;
    int kl = s * 8 + t + 4 * p;
    int word = row * 136 + n * 2 + p;

    if (c < 65) {           // layer 0
        int kap = kap_of(32, c, kl);
        float v = (kap < 2048) ? w2_0[(kap >> 5) * 2048 + (kap & 31) * H64 + n]
                               : b2_0[(kap - 2048) * H64 + n];
        g_w2b0[c * 2176 + word] = tf32r(v);
    }
    {                       // layer 1
        int kap = kap_of(64, c, kl);
        float v = (kap < 4096) ? w2_1[(kap >> 6) * 4096 + (kap & 63) * H64 + n]
                               : b2_1[(kap - 4096) * H64 + n];
        g_w2b1[c * 2176 + word] = tf32r(v);
    }
}

// ---------------- kernel 3: agg = (relu?)x @ root + bias --------------------
template<int IN_C, bool RELU_IN>
__global__ void root_init_kernel(const float* __restrict__ x,
                                 const float* __restrict__ root,
                                 const float* __restrict__ bias,
                                 float* __restrict__ agg)
{
    __shared__ float xr[IN_C];
    int n = blockIdx.x, t = threadIdx.x;
    if (t < IN_C) {
        float v = x[n * IN_C + t];
        xr[t] = RELU_IN ? fmaxf(v, 0.0f) : v;
    }
    __syncthreads();
    float v = __ldg(&bias[t]);
    #pragma unroll
    for (int i = 0; i < IN_C; i++)
        v = fmaf(xr[i], __ldg(&root[i * H64 + t]), v);
    agg[n * H64 + t] = v;
}

// ---------------- kernel 4: fused msg GEMM (mma.sync tf32) + scatter --------
// CTA = 128 edges x 64 outs, 8 warps; warp tile 32 rows x 32 cols
// (mb = w>>1 selects 32-row block, nh = w&1 selects 32-col half).
// x held in registers (xreg[4][8]); B + h streamed via cp.async (triple buf).
template<int IN_C, bool RELU_IN>
__global__ void __launch_bounds__(256, 2)
fused_mma_kernel(const float* __restrict__ x, const int* __restrict__ ei, int E,
                 const float* __restrict__ ht, const uint32_t* __restrict__ w2b,
                 float* __restrict__ agg)
{
    constexpr int NCHUNK = (IN_C == 32) ? 65 : 130;
    constexpr int XROW   = IN_C + 4;
    constexpr int B_OFF  = 0;                 // 3 x 8704
    constexpr int H_OFF  = 26112;             // 3 x 512
    constexpr int X_OFF  = 27648;
    constexpr int DST_OFF = X_OFF + 128 * XROW * 4;

    extern __shared__ char smem[];
    float* x_s   = (float*)(smem + X_OFF);
    float* h_s   = (float*)(smem + H_OFF);
    int*   dst_s = (int*)(smem + DST_OFF);
    uint32_t sbase = smem_u32(smem);

    int tid = threadIdx.x;
    int e0  = blockIdx.x * 128;

    // ---- gather x[src] tile (relu on read for layer 1) ----
    constexpr int XV = IN_C / 4;
    for (int q = tid; q < 128 * XV; q += 256) {
        int e = q / XV, cc = q % XV;
        int ge = e0 + e;
        int s = (ge < E) ? ei[ge] : 0;
        float4 v = *(const float4*)(x + (size_t)s * IN_C + cc * 4);
        if (RELU_IN) {
            v.x = fmaxf(v.x, 0.0f); v.y = fmaxf(v.y, 0.0f);
            v.z = fmaxf(v.z, 0.0f); v.w = fmaxf(v.w, 0.0f);
        }
        *(float4*)&x_s[e * XROW + cc * 4] = v;
    }
    if (tid < 128) dst_s[tid] = (e0 + tid < E) ? ei[E + e0 + tid] : -1;

    // ---- prefetch: B chunk (544 x 16B) + h column (32 x 16B) ----
    auto prefetch = [&](int c) {
        if (c < NCHUNK) {
            int slot = c % 3;
            uint32_t bs = sbase + B_OFF + slot * 8704;
            const char* g = (const char*)w2b + (size_t)c * 8704;
            cp_async16(bs + tid * 16,        g + tid * 16);
            cp_async16(bs + 4096 + tid * 16, g + 4096 + tid * 16);
            if (tid < 32) cp_async16(bs + 8192 + tid * 16, g + 8192 + tid * 16);
            bool isBias = (IN_C == 32) ? (c == 64) : (c == 64 || c == 129);
            if (!isBias && tid < 32) {
                int k = (IN_C == 32) ? c : ((c < 64) ? c : c - 65);
                cp_async16(sbase + H_OFF + slot * 512 + tid * 16,
                           ht + (size_t)k * E + e0 + tid * 4);
            }
        }
        CP_COMMIT();
    };
    prefetch(0);
    prefetch(1);
    __syncthreads();   // x_s / dst_s visible

    const int w    = tid >> 5;
    const int lane = tid & 31;
    const int gid  = lane >> 2;
    const int tig  = lane & 3;
    const int mb   = w >> 1;
    const int nh   = w & 1;

    int rows[4];       // rr = mt*2 + q -> row
    #pragma unroll
    for (int mt = 0; mt < 2; mt++)
        #pragma unroll
        for (int q = 0; q < 2; q++)
            rows[mt * 2 + q] = mb * 32 + mt * 16 + q * 8 + gid;

    float xreg[4][8];
    #pragma unroll
    for (int rr = 0; rr < 4; rr++)
        #pragma unroll
        for (int j = 0; j < 8; j++)
            xreg[rr][j] = x_s[rows[rr] * XROW + tig + 4 * j];

    float acc[2][4][4];
    #pragma unroll
    for (int mt = 0; mt < 2; mt++)
        #pragma unroll
        for (int q = 0; q < 4; q++)
            #pragma unroll
            for (int u = 0; u < 4; u++) acc[mt][q][u] = 0.0f;

    for (int c = 0; c < NCHUNK; c++) {
        if (IN_C == 64 && c == 65) {      // switch to i-half 1
            #pragma unroll
            for (int rr = 0; rr < 4; rr++)
                #pragma unroll
                for (int j = 0; j < 8; j++)
                    xreg[rr][j] = x_s[rows[rr] * XROW + 32 + tig + 4 * j];
        }
        CP_WAIT1();
        __syncthreads();                  // chunk c resident; slot (c+2)%3 free
        prefetch(c + 2);

        int slot = c % 3;
        bool isBias = (IN_C == 32) ? (c == 64) : (c == 64 || c == 129);
        float hv[4];
        if (isBias) {
            #pragma unroll
            for (int rr = 0; rr < 4; rr++) hv[rr] = 1.0f;
        } else {
            const float* hb = h_s + slot * 128;
            #pragma unroll
            for (int rr = 0; rr < 4; rr++) hv[rr] = hb[rows[rr]];
        }

        uint32_t bbase = sbase + B_OFF + slot * 8704 + nh * 256;
        #pragma unroll
        for (int s = 0; s < 4; s++) {
            uint32_t a[2][4];
            #pragma unroll
            for (int mt = 0; mt < 2; mt++) {
                a[mt][0] = tf32r(hv[mt * 2]     * xreg[mt * 2][2 * s]);
                a[mt][1] = tf32r(hv[mt * 2 + 1] * xreg[mt * 2 + 1][2 * s]);
                a[mt][2] = tf32r(hv[mt * 2]     * xreg[mt * 2][2 * s + 1]);
                a[mt][3] = tf32r(hv[mt * 2 + 1] * xreg[mt * 2 + 1][2 * s + 1]);
            }
            uint32_t brow = bbase + (uint32_t)(s * 4 + tig) * 544 + (uint32_t)gid * 8;
            #pragma unroll
            for (int q = 0; q < 4; q++) {
                uint32_t b0, b1;
                asm volatile("ld.shared.v2.b32 {%0, %1}, [%2];"
                             : "=r"(b0), "=r"(b1) : "r"(brow + q * 64));
                mma_tf32(acc[0][q], a[0][0], a[0][1], a[0][2], a[0][3], b0, b1);
                mma_tf32(acc[1][q], a[1][0], a[1][1], a[1][2], a[1][3], b0, b1);
            }
        }
    }

    // ---- scatter-add into agg[dst] ----
    #pragma unroll
    for (int mt = 0; mt < 2; mt++) {
        int d0 = dst_s[rows[mt * 2]];
        int d1 = dst_s[rows[mt * 2 + 1]];
        float* p0 = agg + (size_t)(d0 < 0 ? 0 : d0) * H64;
        float* p1 = agg + (size_t)(d1 < 0 ? 0 : d1) * H64;
        #pragma unroll
        for (int q = 0; q < 4; q++) {
            int n = nh * 32 + q * 8 + tig * 2;
            if (d0 >= 0) {
                atomicAdd(p0 + n,     acc[mt][q][0]);
                atomicAdd(p0 + n + 1, acc[mt][q][1]);
            }
            if (d1 >= 0) {
                atomicAdd(p1 + n,     acc[mt][q][2]);
                atomicAdd(p1 + n + 1, acc[mt][q][3]);
            }
        }
    }
}

// ---------------- kernel 5: out = relu(agg1) --------------------------------
__global__ void relu_out_kernel(const float* __restrict__ in,
                                float* __restrict__ out, int n)
{
    int i = blockIdx.x * blockDim.x + threadIdx.x;
    if (i < n) out[i] = fmaxf(in[i], 0.0f);
}

// ---------------- launch -----------------------------------------------------
extern "C" void kernel_launch(void* const* d_in, const int* in_sizes, int n_in,
                              void* d_out, int out_size)
{
    const float* x      = (const float*)d_in[0];
    const int*   ei     = (const int*)  d_in[1];
    const float* ea     = (const float*)d_in[2];
    const float* w1_0   = (const float*)d_in[3];
    const float* b1_0   = (const float*)d_in[4];
    const float* w2_0   = (const float*)d_in[5];
    const float* b2_0   = (const float*)d_in[6];
    const float* root_0 = (const float*)d_in[7];
    const float* bias_0 = (const float*)d_in[8];
    const float* w1_1   = (const float*)d_in[9];
    const float* b1_1   = (const float*)d_in[10];
    const float* w2_1   = (const float*)d_in[11];
    const float* b2_1   = (const float*)d_in[12];
    const float* root_1 = (const float*)d_in[13];
    const float* bias_1 = (const float*)d_in[14];

    const int N = in_sizes[0] / 32;   // 20000
    const int E = in_sizes[1] / 2;    // 50000

    void* p;
    cudaGetSymbolAddress(&p, g_ht0);  float* ht0  = (float*)p;
    cudaGetSymbolAddress(&p, g_ht1);  float* ht1  = (float*)p;
    cudaGetSymbolAddress(&p, g_w2b0); uint32_t* w2b0 = (uint32_t*)p;
    cudaGetSymbolAddress(&p, g_w2b1); uint32_t* w2b1 = (uint32_t*)p;
    cudaGetSymbolAddress(&p, g_agg0); float* agg0 = (float*)p;
    cudaGetSymbolAddress(&p, g_agg1); float* agg1 = (float*)p;

    const int smem0 = 27648 + 128 * 36 * 4 + 512;   // 46592
    const int smem1 = 27648 + 128 * 68 * 4 + 512;   // 62976
    cudaFuncSetAttribute(fused_mma_kernel<32, false>,
                         cudaFuncAttributeMaxDynamicSharedMemorySize, smem0);
    cudaFuncSetAttribute(fused_mma_kernel<64, true>,
                         cudaFuncAttributeMaxDynamicSharedMemorySize, smem1);

    const int threads = 256;
    dim3 grid_h((E + threads - 1) / threads, H64, 2);
    const int grid_fuse = (E + 127) / 128;
    const int grid_relu = (N * H64 + threads - 1) / threads;

    edge_mlp_both_kernel<<<grid_h, threads>>>(ea, w1_0, b1_0, w1_1, b1_1, ht0, ht1, E);
    prep_both_kernel<<<(130 * 2048 + threads - 1) / threads, threads>>>(w2_0, b2_0, w2_1, b2_1);

    // layer 0
    root_init_kernel<32, false><<<N, H64>>>(x, root_0, bias_0, agg0);
    fused_mma_kernel<32, false><<<grid_fuse, threads, smem0>>>(x, ei, E, ht0, w2b0, agg0);

    // layer 1 (relu fused into readers)
    root_init_kernel<64, true><<<N, H64>>>(agg0, root_1, bias_1, agg1);
    fused_mma_kernel<64, true><<<grid_fuse, threads, smem1>>>(agg0, ei, E, ht1, w2b1, agg1);

    relu_out_kernel<<<grid_relu, threads>>>(agg1, (float*)d_out, N * H64);
}

// round 6
// speedup vs baseline: 1.4223x; 1.4223x over previous
#include <cuda_runtime.h>
#include <cuda_fp16.h>
#include <cstdint>

#define H64 64
#define EE_MAX 50000
#define NN_MAX 20000

// ---------------- scratch (static device globals) ---------------------------
__device__ float    g_ht0[EE_MAX * H64 + 256];
__device__ float    g_ht1[EE_MAX * H64 + 256];
__device__ uint32_t g_w2bh0[65 * 1088];     // fp16x2 packed B chunks, layer 0
__device__ uint32_t g_w2bh1[130 * 1088];    // fp16x2 packed B chunks, layer 1
__device__ float    g_agg0[NN_MAX * H64];
__device__ float    g_agg1[NN_MAX * H64];

// ---------------- PTX helpers ------------------------------------------------
__device__ __forceinline__ uint32_t smem_u32(const void* p) {
    return (uint32_t)__cvta_generic_to_shared(p);
}
__device__ __forceinline__ void cp_async16(uint32_t s, const void* g) {
    asm volatile("cp.async.cg.shared.global [%0], [%1], 16;" :: "r"(s), "l"(g));
}
#define CP_COMMIT() asm volatile("cp.async.commit_group;" ::: "memory")
#define CP_WAIT1()  asm volatile("cp.async.wait_group 1;" ::: "memory")

// pack {lo=v0, hi=v1} as fp16x2
__device__ __forceinline__ uint32_t packf16(float v0, float v1) {
    uint32_t d;
    asm("cvt.rn.f16x2.f32 %0, %1, %2;" : "=r"(d) : "f"(v1), "f"(v0));
    return d;
}

__device__ __forceinline__ void mma_f16(float* d, uint32_t a0, uint32_t a1,
                                        uint32_t a2, uint32_t a3,
                                        uint32_t b0, uint32_t b1) {
    asm volatile(
        "mma.sync.aligned.m16n8k16.row.col.f32.f16.f16.f32 "
        "{%0,%1,%2,%3}, {%4,%5,%6,%7}, {%8,%9}, {%0,%1,%2,%3};"
        : "+f"(d[0]), "+f"(d[1]), "+f"(d[2]), "+f"(d[3])
        : "r"(a0), "r"(a1), "r"(a2), "r"(a3), "r"(b0), "r"(b1));
}

// ---------------- chunk->kap mapping (reordered for i-half locality) --------
// L0 (IN=32): c in [0,64): k=c            kap = c*32 + kl
//             c == 64   : bias           kap = 2048 + kl
// L1 (IN=64): c in [0,64): k=c, half 0    kap = c*64 + kl
//             c == 64   : bias, half 0   kap = 4096 + kl
//             c in [65,129): k=c-65, h1   kap = (c-65)*64 + 32 + kl
//             c == 129  : bias, half 1   kap = 4128 + kl
__host__ __device__ __forceinline__ int kap_of(int IN_C, int c, int kl) {
    if (IN_C == 32) return (c < 64) ? c * 32 + kl : 2048 + kl;
    if (c < 64)  return c * 64 + kl;
    if (c == 64) return 4096 + kl;
    if (c < 129) return (c - 65) * 64 + 32 + kl;
    return 4128 + kl;
}

// ---------------- kernel 1: both edge MLPs, h^T stored [j][e] ---------------
__global__ void edge_mlp_both_kernel(const float* __restrict__ ea,
                                     const float* __restrict__ w1_0,
                                     const float* __restrict__ b1_0,
                                     const float* __restrict__ w1_1,
                                     const float* __restrict__ b1_1,
                                     float* __restrict__ ht0,
                                     float* __restrict__ ht1, int E)
{
    int e = blockIdx.x * blockDim.x + threadIdx.x;
    int j = blockIdx.y;
    if (e >= E) return;
    float a0 = __ldg(&ea[2 * e]);
    float a1 = __ldg(&ea[2 * e + 1]);
    const float* w1 = blockIdx.z ? w1_1 : w1_0;
    const float* b1 = blockIdx.z ? b1_1 : b1_0;
    float* ht       = blockIdx.z ? ht1  : ht0;
    float v = fmaf(a0, __ldg(&w1[j]), fmaf(a1, __ldg(&w1[H64 + j]), __ldg(&b1[j])));
    ht[(size_t)j * E + e] = fmaxf(v, 0.0f);
}

// ---------------- kernel 2: pack both fp16 B tables (m16n8k16 b-frag layout)
// chunk c: row = s*4 + t (s=k16 step 0..1, t = k%... tig), pair p (k offset 8p)
//   fp16x2 word = { B[kl0][n], B[kl0+1][n] },  kl0 = s*16 + 2t + 8p
// word offset in chunk: row*136 + n*2 + p    (row stride 136 words = 544 B)
__global__ void prep_both_kernel(const float* __restrict__ w2_0,
                                 const float* __restrict__ b2_0,
                                 const float* __restrict__ w2_1,
                                 const float* __restrict__ b2_1)
{
    int idx = blockIdx.x * blockDim.x + threadIdx.x;
    if (idx >= 130 * 1024) return;
    int c = idx >> 10, rem = idx & 1023;
    int row = rem >> 7;            // 0..7
    int n   = (rem >> 1) & 63;
    int p   = rem & 1;
    int s = row >> 2, t = row & 3;
    int kl0 = s * 16 + 2 * t + 8 * p;
    int word = row * 136 + n * 2 + p;

    if (c < 65) {       // layer 0
        int ka = kap_of(32, c, kl0), kb = kap_of(32, c, kl0 + 1);
        float v0 = (ka < 2048) ? w2_0[(ka >> 5) * 2048 + (ka & 31) * H64 + n]
                               : b2_0[(ka - 2048) * H64 + n];
        float v1 = (kb < 2048) ? w2_0[(kb >> 5) * 2048 + (kb & 31) * H64 + n]
                               : b2_0[(kb - 2048) * H64 + n];
        g_w2bh0[c * 1088 + word] = packf16(v0, v1);
    }
    {                   // layer 1
        int ka = kap_of(64, c, kl0), kb = kap_of(64, c, kl0 + 1);
        float v0 = (ka < 4096) ? w2_1[(ka >> 6) * 4096 + (ka & 63) * H64 + n]
                               : b2_1[(ka - 4096) * H64 + n];
        float v1 = (kb < 4096) ? w2_1[(kb >> 6) * 4096 + (kb & 63) * H64 + n]
                               : b2_1[(kb - 4096) * H64 + n];
        g_w2bh1[c * 1088 + word] = packf16(v0, v1);
    }
}

// ---------------- kernel 3: agg = (relu?)x @ root + bias --------------------
template<int IN_C, bool RELU_IN>
__global__ void root_init_kernel(const float* __restrict__ x,
                                 const float* __restrict__ root,
                                 const float* __restrict__ bias,
                                 float* __restrict__ agg)
{
    __shared__ float xr[IN_C];
    int n = blockIdx.x, t = threadIdx.x;
    if (t < IN_C) {
        float v = x[n * IN_C + t];
        xr[t] = RELU_IN ? fmaxf(v, 0.0f) : v;
    }
    __syncthreads();
    float v = __ldg(&bias[t]);
    #pragma unroll
    for (int i = 0; i < IN_C; i++)
        v = fmaf(xr[i], __ldg(&root[i * H64 + t]), v);
    agg[n * H64 + t] = v;
}

// ---------------- kernel 4: fused msg GEMM (mma.sync fp16) + scatter --------
// CTA = 128 edges x 64 outs, 8 warps; warp tile 32 rows x 32 cols.
// A[e, kap] = fp16(h[e]*x[src,i]); B fp16 streamed via cp.async (triple buf).
template<int IN_C, bool RELU_IN>
__global__ void __launch_bounds__(256, 2)
fused_mma_kernel(const float* __restrict__ x, const int* __restrict__ ei, int E,
                 const float* __restrict__ ht, const uint32_t* __restrict__ w2b,
                 float* __restrict__ agg)
{
    constexpr int NCHUNK = (IN_C == 32) ? 65 : 130;
    constexpr int XROW   = IN_C + 4;
    constexpr int B_OFF  = 0;                 // 3 x 4352
    constexpr int H_OFF  = 13056;             // 3 x 512
    constexpr int X_OFF  = 14592;
    constexpr int DST_OFF = X_OFF + 128 * XROW * 4;

    extern __shared__ char smem[];
    float* x_s   = (float*)(smem + X_OFF);
    float* h_s   = (float*)(smem + H_OFF);
    int*   dst_s = (int*)(smem + DST_OFF);
    uint32_t sbase = smem_u32(smem);

    int tid = threadIdx.x;
    int e0  = blockIdx.x * 128;

    // ---- gather x[src] tile (relu on read for layer 1) ----
    constexpr int XV = IN_C / 4;
    for (int q = tid; q < 128 * XV; q += 256) {
        int e = q / XV, cc = q % XV;
        int ge = e0 + e;
        int s = (ge < E) ? ei[ge] : 0;
        float4 v = *(const float4*)(x + (size_t)s * IN_C + cc * 4);
        if (RELU_IN) {
            v.x = fmaxf(v.x, 0.0f); v.y = fmaxf(v.y, 0.0f);
            v.z = fmaxf(v.z, 0.0f); v.w = fmaxf(v.w, 0.0f);
        }
        *(float4*)&x_s[e * XROW + cc * 4] = v;
    }
    if (tid < 128) dst_s[tid] = (e0 + tid < E) ? ei[E + e0 + tid] : -1;

    // ---- prefetch: B chunk (272 x 16B) + h column (32 x 16B) ----
    auto prefetch = [&](int c) {
        if (c < NCHUNK) {
            int slot = c % 3;
            uint32_t bs = sbase + B_OFF + slot * 4352;
            const char* g = (const char*)w2b + (size_t)c * 4352;
            cp_async16(bs + tid * 16, g + tid * 16);
            if (tid < 16) cp_async16(bs + 4096 + tid * 16, g + 4096 + tid * 16);
            bool isBias = (IN_C == 32) ? (c == 64) : (c == 64 || c == 129);
            if (!isBias && tid < 32) {
                int k = (IN_C == 32) ? c : ((c < 64) ? c : c - 65);
                cp_async16(sbase + H_OFF + slot * 512 + tid * 16,
                           ht + (size_t)k * E + e0 + tid * 4);
            }
        }
        CP_COMMIT();
    };
    prefetch(0);
    prefetch(1);
    __syncthreads();   // x_s / dst_s visible

    const int w    = tid >> 5;
    const int lane = tid & 31;
    const int gid  = lane >> 2;
    const int tig  = lane & 3;
    const int mb   = w >> 1;
    const int nh   = w & 1;

    int rows[4];       // rr = mt*2 + q -> row (q=0: gid, q=1: gid+8)
    #pragma unroll
    for (int mt = 0; mt < 2; mt++)
        #pragma unroll
        for (int q = 0; q < 2; q++)
            rows[mt * 2 + q] = mb * 32 + mt * 16 + q * 8 + gid;

    // xreg[rr][j], j = s*4 + p*2 + u  ->  i = ih + s*16 + 2*tig + 8*p + u
    float xreg[4][8];
    #pragma unroll
    for (int rr = 0; rr < 4; rr++)
        #pragma unroll
        for (int s = 0; s < 2; s++)
            #pragma unroll
            for (int pu = 0; pu < 4; pu++)
                xreg[rr][s * 4 + pu] =
                    x_s[rows[rr] * XROW + s * 16 + 2 * tig + 8 * (pu >> 1) + (pu & 1)];

    float acc[2][4][4];
    #pragma unroll
    for (int mt = 0; mt < 2; mt++)
        #pragma unroll
        for (int q = 0; q < 4; q++)
            #pragma unroll
            for (int u = 0; u < 4; u++) acc[mt][q][u] = 0.0f;

    for (int c = 0; c < NCHUNK; c++) {
        if (IN_C == 64 && c == 65) {      // switch x regs to i-half 1
            #pragma unroll
            for (int rr = 0; rr < 4; rr++)
                #pragma unroll
                for (int s = 0; s < 2; s++)
                    #pragma unroll
                    for (int pu = 0; pu < 4; pu++)
                        xreg[rr][s * 4 + pu] =
                            x_s[rows[rr] * XROW + 32 + s * 16 + 2 * tig + 8 * (pu >> 1) + (pu & 1)];
        }
        CP_WAIT1();
        __syncthreads();                  // chunk c resident; slot (c+2)%3 free
        prefetch(c + 2);

        int slot = c % 3;
        bool isBias = (IN_C == 32) ? (c == 64) : (c == 64 || c == 129);
        float hv[4];
        if (isBias) {
            #pragma unroll
            for (int rr = 0; rr < 4; rr++) hv[rr] = 1.0f;
        } else {
            const float* hb = h_s + slot * 128;
            #pragma unroll
            for (int rr = 0; rr < 4; rr++) hv[rr] = hb[rows[rr]];
        }

        uint32_t bbase = sbase + B_OFF + slot * 4352 + nh * 256;
        #pragma unroll
        for (int s = 0; s < 2; s++) {
            uint32_t a[2][4];
            #pragma unroll
            for (int mt = 0; mt < 2; mt++) {
                float h0 = hv[mt * 2], h1 = hv[mt * 2 + 1];
                const float* x0 = xreg[mt * 2];
                const float* x1 = xreg[mt * 2 + 1];
                a[mt][0] = packf16(h0 * x0[s * 4 + 0], h0 * x0[s * 4 + 1]);
                a[mt][1] = packf16(h1 * x1[s * 4 + 0], h1 * x1[s * 4 + 1]);
                a[mt][2] = packf16(h0 * x0[s * 4 + 2], h0 * x0[s * 4 + 3]);
                a[mt][3] = packf16(h1 * x1[s * 4 + 2], h1 * x1[s * 4 + 3]);
            }
            uint32_t brow = bbase + (uint32_t)(s * 4 + tig) * 544 + (uint32_t)gid * 8;
            #pragma unroll
            for (int q = 0; q < 4; q++) {
                uint32_t b0, b1;
                asm volatile("ld.shared.v2.b32 {%0, %1}, [%2];"
                             : "=r"(b0), "=r"(b1) : "r"(brow + q * 64));
                mma_f16(acc[0][q], a[0][0], a[0][1], a[0][2], a[0][3], b0, b1);
                mma_f16(acc[1][q], a[1][0], a[1][1], a[1][2], a[1][3], b0, b1);
            }
        }
    }

    // ---- scatter-add into agg[dst] ----
    #pragma unroll
    for (int mt = 0; mt < 2; mt++) {
        int d0 = dst_s[rows[mt * 2]];
        int d1 = dst_s[rows[mt * 2 + 1]];
        float* p0 = agg + (size_t)(d0 < 0 ? 0 : d0) * H64;
        float* p1 = agg + (size_t)(d1 < 0 ? 0 : d1) * H64;
        #pragma unroll
        for (int q = 0; q < 4; q++) {
            int n = nh * 32 + q * 8 + tig * 2;
            if (d0 >= 0) {
                atomicAdd(p0 + n,     acc[mt][q][0]);
                atomicAdd(p0 + n + 1, acc[mt][q][1]);
            }
            if (d1 >= 0) {
                atomicAdd(p1 + n,     acc[mt][q][2]);
                atomicAdd(p1 + n + 1, acc[mt][q][3]);
            }
        }
    }
}

// ---------------- kernel 5: out = relu(agg1) --------------------------------
__global__ void relu_out_kernel(const float* __restrict__ in,
                                float* __restrict__ out, int n)
{
    int i = blockIdx.x * blockDim.x + threadIdx.x;
    if (i < n) out[i] = fmaxf(in[i], 0.0f);
}

// ---------------- launch -----------------------------------------------------
extern "C" void kernel_launch(void* const* d_in, const int* in_sizes, int n_in,
                              void* d_out, int out_size)
{
    const float* x      = (const float*)d_in[0];
    const int*   ei     = (const int*)  d_in[1];
    const float* ea     = (const float*)d_in[2];
    const float* w1_0   = (const float*)d_in[3];
    const float* b1_0   = (const float*)d_in[4];
    const float* w2_0   = (const float*)d_in[5];
    const float* b2_0   = (const float*)d_in[6];
    const float* root_0 = (const float*)d_in[7];
    const float* bias_0 = (const float*)d_in[8];
    const float* w1_1   = (const float*)d_in[9];
    const float* b1_1   = (const float*)d_in[10];
    const float* w2_1   = (const float*)d_in[11];
    const float* b2_1   = (const float*)d_in[12];
    const float* root_1 = (const float*)d_in[13];
    const float* bias_1 = (const float*)d_in[14];

    const int N = in_sizes[0] / 32;   // 20000
    const int E = in_sizes[1] / 2;    // 50000

    void* p;
    cudaGetSymbolAddress(&p, g_ht0);   float* ht0  = (float*)p;
    cudaGetSymbolAddress(&p, g_ht1);   float* ht1  = (float*)p;
    cudaGetSymbolAddress(&p, g_w2bh0); uint32_t* w2b0 = (uint32_t*)p;
    cudaGetSymbolAddress(&p, g_w2bh1); uint32_t* w2b1 = (uint32_t*)p;
    cudaGetSymbolAddress(&p, g_agg0);  float* agg0 = (float*)p;
    cudaGetSymbolAddress(&p, g_agg1);  float* agg1 = (float*)p;

    const int smem0 = 14592 + 128 * 36 * 4 + 512;   // 33536
    const int smem1 = 14592 + 128 * 68 * 4 + 512;   // 49920
    cudaFuncSetAttribute(fused_mma_kernel<32, false>,
                         cudaFuncAttributeMaxDynamicSharedMemorySize, smem0);
    cudaFuncSetAttribute(fused_mma_kernel<64, true>,
                         cudaFuncAttributeMaxDynamicSharedMemorySize, smem1);

    const int threads = 256;
    dim3 grid_h((E + threads - 1) / threads, H64, 2);
    const int grid_fuse = (E + 127) / 128;
    const int grid_relu = (N * H64 + threads - 1) / threads;

    edge_mlp_both_kernel<<<grid_h, threads>>>(ea, w1_0, b1_0, w1_1, b1_1, ht0, ht1, E);
    prep_both_kernel<<<(130 * 1024 + threads - 1) / threads, threads>>>(w2_0, b2_0, w2_1, b2_1);

    // layer 0
    root_init_kernel<32, false><<<N, H64>>>(x, root_0, bias_0, agg0);
    fused_mma_kernel<32, false><<<grid_fuse, threads, smem0>>>(x, ei, E, ht0, w2b0, agg0);

    // layer 1 (relu fused into readers)
    root_init_kernel<64, true><<<N, H64>>>(agg0, root_1, bias_1, agg1);
    fused_mma_kernel<64, true><<<grid_fuse, threads, smem1>>>(agg0, ei, E, ht1, w2b1, agg1);

    relu_out_kernel<<<grid_relu, threads>>>(agg1, (float*)d_out, N * H64);
}

// round 7
// speedup vs baseline: 1.6429x; 1.1551x over previous
#include <cuda_runtime.h>
#include <cuda_fp16.h>
#include <cstdint>

#define H64 64
#define EE_MAX 50000
#define NN_MAX 20000

// ---------------- scratch (static device globals) ---------------------------
__device__ float    g_ht0[EE_MAX * H64 + 256];
__device__ float    g_ht1[EE_MAX * H64 + 256];
__device__ uint32_t g_w2bh0[33 * 2176];     // fp16x2 packed B chunk64s, layer 0
__device__ uint32_t g_w2bh1[66 * 2176];     // fp16x2 packed B chunk64s, layer 1
__device__ float    g_agg0[NN_MAX * H64];
__device__ float    g_agg1[NN_MAX * H64];

// ---------------- PTX helpers ------------------------------------------------
__device__ __forceinline__ uint32_t smem_u32(const void* p) {
    return (uint32_t)__cvta_generic_to_shared(p);
}
__device__ __forceinline__ void cp_async16(uint32_t s, const void* g) {
    asm volatile("cp.async.cg.shared.global [%0], [%1], 16;" :: "r"(s), "l"(g));
}
#define CP_COMMIT() asm volatile("cp.async.commit_group;" ::: "memory")
#define CP_WAIT1()  asm volatile("cp.async.wait_group 1;" ::: "memory")

// pack {lo=v0, hi=v1} as fp16x2
__device__ __forceinline__ uint32_t packf16(float v0, float v1) {
    uint32_t d;
    asm("cvt.rn.f16x2.f32 %0, %1, %2;" : "=r"(d) : "f"(v1), "f"(v0));
    return d;
}

__device__ __forceinline__ void mma_f16(float* d, uint32_t a0, uint32_t a1,
                                        uint32_t a2, uint32_t a3,
                                        uint32_t b0, uint32_t b1) {
    asm volatile(
        "mma.sync.aligned.m16n8k16.row.col.f32.f16.f16.f32 "
        "{%0,%1,%2,%3}, {%4,%5,%6,%7}, {%8,%9}, {%0,%1,%2,%3};"
        : "+f"(d[0]), "+f"(d[1]), "+f"(d[2]), "+f"(d[3])
        : "r"(a0), "r"(a1), "r"(a2), "r"(a3), "r"(b0), "r"(b1));
}

// ---------------- kernel 1: both edge MLPs, h^T stored [j][e] ---------------
__global__ void edge_mlp_both_kernel(const float* __restrict__ ea,
                                     const float* __restrict__ w1_0,
                                     const float* __restrict__ b1_0,
                                     const float* __restrict__ w1_1,
                                     const float* __restrict__ b1_1,
                                     float* __restrict__ ht0,
                                     float* __restrict__ ht1, int E)
{
    int e = blockIdx.x * blockDim.x + threadIdx.x;
    int j = blockIdx.y;
    if (e >= E) return;
    float a0 = __ldg(&ea[2 * e]);
    float a1 = __ldg(&ea[2 * e + 1]);
    const float* w1 = blockIdx.z ? w1_1 : w1_0;
    const float* b1 = blockIdx.z ? b1_1 : b1_0;
    float* ht       = blockIdx.z ? ht1  : ht0;
    float v = fmaf(a0, __ldg(&w1[j]), fmaf(a1, __ldg(&w1[H64 + j]), __ldg(&b1[j])));
    ht[(size_t)j * E + e] = fmaxf(v, 0.0f);
}

// ---------------- kernel 2: pack fp16 B chunk64 tables ----------------------
// chunk64 c: 16 rows (row = s*4 + t; s = k16-step 0..3), 64 cols n, pair p.
//   fp16x2 word = { B[kap(k0)][n], B[kap(k0+1)][n] },  k0 = 2t + 8p (kappa)
//   network k = 2c' + (s>>1);  i = ihalf*32 + (s&1)*16 + kappa
// word offset in chunk: row*136 + n*2 + p (row stride 136 words = 544 B)
// L0 (33 chunks): c<32 data; c==32 bias (s<2), zeros (s>=2)
// L1 (66 chunks): c<33 half0 (c==32 bias+zeros); c in [33,66) half1 likewise
__global__ void prep_both_kernel(const float* __restrict__ w2_0,
                                 const float* __restrict__ b2_0,
                                 const float* __restrict__ w2_1,
                                 const float* __restrict__ b2_1)
{
    int idx = blockIdx.x * blockDim.x + threadIdx.x;
    if (idx >= 66 * 2048) return;
    int c = idx >> 11, rem = idx & 2047;
    int row = rem >> 7;            // 0..15
    int n   = (rem >> 1) & 63;
    int p   = rem & 1;
    int s = row >> 2, t = row & 3;
    int k0 = 2 * t + 8 * p;        // kappa for u=0; u=1 is k0+1
    int word = row * 136 + n * 2 + p;

    if (c < 33) {       // layer 0 (ih = 0)
        float v0 = 0.f, v1 = 0.f;
        if (c < 32) {
            int k = 2 * c + (s >> 1);
            int i = (s & 1) * 16 + k0;
            v0 = w2_0[k * 2048 + i * H64 + n];
            v1 = w2_0[k * 2048 + (i + 1) * H64 + n];
        } else if (s < 2) {
            int i = s * 16 + k0;
            v0 = b2_0[i * H64 + n];
            v1 = b2_0[(i + 1) * H64 + n];
        }
        g_w2bh0[c * 2176 + word] = packf16(v0, v1);
    }
    {                   // layer 1
        int ih = (c >= 33) ? 1 : 0;
        int cc = c - 33 * ih;
        float v0 = 0.f, v1 = 0.f;
        if (cc < 32) {
            int k = 2 * cc + (s >> 1);
            int i = ih * 32 + (s & 1) * 16 + k0;
            v0 = w2_1[k * 4096 + i * H64 + n];
            v1 = w2_1[k * 4096 + (i + 1) * H64 + n];
        } else if (s < 2) {
            int i = ih * 32 + s * 16 + k0;
            v0 = b2_1[i * H64 + n];
            v1 = b2_1[(i + 1) * H64 + n];
        }
        g_w2bh1[c * 2176 + word] = packf16(v0, v1);
    }
}

// ---------------- kernel 3: agg = (relu?)x @ root + bias --------------------
template<int IN_C, bool RELU_IN>
__global__ void root_init_kernel(const float* __restrict__ x,
                                 const float* __restrict__ root,
                                 const float* __restrict__ bias,
                                 float* __restrict__ agg)
{
    __shared__ float xr[IN_C];
    int n = blockIdx.x, t = threadIdx.x;
    if (t < IN_C) {
        float v = x[n * IN_C + t];
        xr[t] = RELU_IN ? fmaxf(v, 0.0f) : v;
    }
    __syncthreads();
    float v = __ldg(&bias[t]);
    #pragma unroll
    for (int i = 0; i < IN_C; i++)
        v = fmaf(xr[i], __ldg(&root[i * H64 + t]), v);
    agg[n * H64 + t] = v;
}

// ---------------- kernel 4: fused msg GEMM (mma.sync fp16) + scatter --------
// CTA = 64 edges x 64 outs, 4 warps; warp tile 16 rows x 64 cols.
// K-chunks of 64 (2 network-k x 32 i), triple-buffered cp.async for B + h.
template<int IN_C, bool RELU_IN>
__global__ void __launch_bounds__(128, 4)
fused_mma_kernel(const float* __restrict__ x, const int* __restrict__ ei, int E,
                 const float* __restrict__ ht, const uint32_t* __restrict__ w2b,
                 float* __restrict__ agg)
{
    constexpr int NCHUNK = (IN_C == 32) ? 33 : 66;
    constexpr int XROW   = IN_C + 4;
    constexpr int B_OFF  = 0;                 // 3 x 8704
    constexpr int H_OFF  = 26112;             // 3 x 512  ([slot][kk 0..1][e 0..63])
    constexpr int X_OFF  = 27648;
    constexpr int DST_OFF = X_OFF + 64 * XROW * 4;

    extern __shared__ char smem[];
    float* x_s   = (float*)(smem + X_OFF);
    float* h_s   = (float*)(smem + H_OFF);
    int*   dst_s = (int*)(smem + DST_OFF);
    uint32_t sbase = smem_u32(smem);

    int tid = threadIdx.x;
    int e0  = blockIdx.x * 64;

    // ---- gather x[src] tile (relu on read for layer 1) ----
    constexpr int XV = IN_C / 4;
    for (int q = tid; q < 64 * XV; q += 128) {
        int e = q / XV, cc = q % XV;
        int ge = e0 + e;
        int s = (ge < E) ? ei[ge] : 0;
        float4 v = *(const float4*)(x + (size_t)s * IN_C + cc * 4);
        if (RELU_IN) {
            v.x = fmaxf(v.x, 0.0f); v.y = fmaxf(v.y, 0.0f);
            v.z = fmaxf(v.z, 0.0f); v.w = fmaxf(v.w, 0.0f);
        }
        *(float4*)&x_s[e * XROW + cc * 4] = v;
    }
    if (tid < 64) dst_s[tid] = (e0 + tid < E) ? ei[E + e0 + tid] : -1;

    // ---- prefetch: B chunk (8704 B) + 2 h columns (512 B) ----
    auto prefetch = [&](int c) {
        if (c < NCHUNK) {
            int slot = c % 3;
            uint32_t bs = sbase + B_OFF + slot * 8704;
            const char* g = (const char*)w2b + (size_t)c * 8704;
            #pragma unroll
            for (int o = 0; o < 8192; o += 2048)
                cp_async16(bs + o + tid * 16, g + o + tid * 16);
            if (tid < 32) cp_async16(bs + 8192 + tid * 16, g + 8192 + tid * 16);
            bool isBias = (IN_C == 32) ? (c == 32) : (c == 32 || c == 65);
            if (!isBias && tid < 32) {
                int cc = (IN_C == 32) ? c : ((c < 33) ? c : c - 33);
                int kk = tid >> 4, ln = tid & 15;
                cp_async16(sbase + H_OFF + slot * 512 + kk * 256 + ln * 16,
                           ht + (size_t)(2 * cc + kk) * E + e0 + ln * 4);
            }
        }
        CP_COMMIT();
    };
    prefetch(0);
    prefetch(1);
    __syncthreads();   // x_s / dst_s visible

    const int w    = tid >> 5;
    const int lane = tid & 31;
    const int gid  = lane >> 2;
    const int tig  = lane & 3;
    const int r0   = w * 16 + gid;     // rows r0 and r0+8

    // xreg[r][j], j = m*4 + p*2 + u -> i = ih + m*16 + 2*tig + 8*p + u
    float xreg[2][8];
    auto load_xreg = [&](int ih) {
        #pragma unroll
        for (int r = 0; r < 2; r++)
            #pragma unroll
            for (int j = 0; j < 8; j++)
                xreg[r][j] = x_s[(r0 + r * 8) * XROW + ih +
                                 (j >> 2) * 16 + 2 * tig + 8 * ((j >> 1) & 1) + (j & 1)];
    };
    load_xreg(0);

    float acc[8][4];
    #pragma unroll
    for (int q = 0; q < 8; q++)
        #pragma unroll
        for (int u = 0; u < 4; u++) acc[q][u] = 0.0f;

    for (int c = 0; c < NCHUNK; c++) {
        if (IN_C == 64 && c == 33) load_xreg(32);   // switch to i-half 1
        CP_WAIT1();
        __syncthreads();                  // chunk c resident; slot (c+2)%3 free
        prefetch(c + 2);

        int slot = c % 3;
        bool isBias = (IN_C == 32) ? (c == 32) : (c == 32 || c == 65);
        float hk[2][2];                   // [kk][row]
        if (isBias) {
            hk[0][0] = hk[0][1] = hk[1][0] = hk[1][1] = 1.0f;
        } else {
            const float* hb = h_s + slot * 128;
            hk[0][0] = hb[r0];      hk[0][1] = hb[r0 + 8];
            hk[1][0] = hb[64 + r0]; hk[1][1] = hb[64 + r0 + 8];
        }

        uint32_t bbase = sbase + B_OFF + slot * 8704;
        #pragma unroll
        for (int s = 0; s < 4; s++) {
            float h0 = hk[s >> 1][0], h1 = hk[s >> 1][1];
            int jb = (s & 1) * 4;
            uint32_t a0 = packf16(h0 * xreg[0][jb + 0], h0 * xreg[0][jb + 1]);
            uint32_t a1 = packf16(h1 * xreg[1][jb + 0], h1 * xreg[1][jb + 1]);
            uint32_t a2 = packf16(h0 * xreg[0][jb + 2], h0 * xreg[0][jb + 3]);
            uint32_t a3 = packf16(h1 * xreg[1][jb + 2], h1 * xreg[1][jb + 3]);
            uint32_t brow = bbase + (uint32_t)(s * 4 + tig) * 544 + (uint32_t)gid * 8;
            #pragma unroll
            for (int q = 0; q < 8; q++) {
                uint32_t b0, b1;
                asm volatile("ld.shared.v2.b32 {%0, %1}, [%2];"
                             : "=r"(b0), "=r"(b1) : "r"(brow + q * 64));
                mma_f16(acc[q], a0, a1, a2, a3, b0, b1);
            }
        }
    }

    // ---- scatter-add into agg[dst] ----
    int d0 = dst_s[r0], d1 = dst_s[r0 + 8];
    float* p0 = agg + (size_t)(d0 < 0 ? 0 : d0) * H64;
    float* p1 = agg + (size_t)(d1 < 0 ? 0 : d1) * H64;
    #pragma unroll
    for (int q = 0; q < 8; q++) {
        int n = q * 8 + tig * 2;
        if (d0 >= 0) {
            atomicAdd(p0 + n,     acc[q][0]);
            atomicAdd(p0 + n + 1, acc[q][1]);
        }
        if (d1 >= 0) {
            atomicAdd(p1 + n,     acc[q][2]);
            atomicAdd(p1 + n + 1, acc[q][3]);
        }
    }
}

// ---------------- kernel 5: out = relu(agg1) --------------------------------
__global__ void relu_out_kernel(const float* __restrict__ in,
                                float* __restrict__ out, int n)
{
    int i = blockIdx.x * blockDim.x + threadIdx.x;
    if (i < n) out[i] = fmaxf(in[i], 0.0f);
}

// ---------------- launch -----------------------------------------------------
extern "C" void kernel_launch(void* const* d_in, const int* in_sizes, int n_in,
                              void* d_out, int out_size)
{
    const float* x      = (const float*)d_in[0];
    const int*   ei     = (const int*)  d_in[1];
    const float* ea     = (const float*)d_in[2];
    const float* w1_0   = (const float*)d_in[3];
    const float* b1_0   = (const float*)d_in[4];
    const float* w2_0   = (const float*)d_in[5];
    const float* b2_0   = (const float*)d_in[6];
    const float* root_0 = (const float*)d_in[7];
    const float* bias_0 = (const float*)d_in[8];
    const float* w1_1   = (const float*)d_in[9];
    const float* b1_1   = (const float*)d_in[10];
    const float* w2_1   = (const float*)d_in[11];
    const float* b2_1   = (const float*)d_in[12];
    const float* root_1 = (const float*)d_in[13];
    const float* bias_1 = (const float*)d_in[14];

    const int N = in_sizes[0] / 32;   // 20000
    const int E = in_sizes[1] / 2;    // 50000

    void* p;
    cudaGetSymbolAddress(&p, g_ht0);   float* ht0  = (float*)p;
    cudaGetSymbolAddress(&p, g_ht1);   float* ht1  = (float*)p;
    cudaGetSymbolAddress(&p, g_w2bh0); uint32_t* w2b0 = (uint32_t*)p;
    cudaGetSymbolAddress(&p, g_w2bh1); uint32_t* w2b1 = (uint32_t*)p;
    cudaGetSymbolAddress(&p, g_agg0);  float* agg0 = (float*)p;
    cudaGetSymbolAddress(&p, g_agg1);  float* agg1 = (float*)p;

    const int smem0 = 27648 + 64 * 36 * 4 + 256;   // 37120
    const int smem1 = 27648 + 64 * 68 * 4 + 256;   // 45312
    cudaFuncSetAttribute(fused_mma_kernel<32, false>,
                         cudaFuncAttributeMaxDynamicSharedMemorySize, smem0);
    cudaFuncSetAttribute(fused_mma_kernel<64, true>,
                         cudaFuncAttributeMaxDynamicSharedMemorySize, smem1);

    const int threads = 256;
    dim3 grid_h((E + threads - 1) / threads, H64, 2);
    const int grid_fuse = (E + 63) / 64;
    const int grid_relu = (N * H64 + threads - 1) / threads;

    edge_mlp_both_kernel<<<grid_h, threads>>>(ea, w1_0, b1_0, w1_1, b1_1, ht0, ht1, E);
    prep_both_kernel<<<(66 * 2048 + threads - 1) / threads, threads>>>(w2_0, b2_0, w2_1, b2_1);

    // layer 0
    root_init_kernel<32, false><<<N, H64>>>(x, root_0, bias_0, agg0);
    fused_mma_kernel<32, false><<<grid_fuse, 128, smem0>>>(x, ei, E, ht0, w2b0, agg0);

    // layer 1 (relu fused into readers)
    root_init_kernel<64, true><<<N, H64>>>(agg0, root_1, bias_1, agg1);
    fused_mma_kernel<64, true><<<grid_fuse, 128, smem1>>>(agg0, ei, E, ht1, w2b1, agg1);

    relu_out_kernel<<<grid_relu, threads>>>(agg1, (float*)d_out, N * H64);
}

// round 8
// speedup vs baseline: 1.8017x; 1.0967x over previous
#include <cuda_runtime.h>
#include <cuda_fp16.h>
#include <cstdint>

#define H64 64
#define EE_MAX 50000
#define NN_MAX 20000

// ---------------- scratch (static device globals) ---------------------------
__device__ float    g_ht0[EE_MAX * H64 + 256];
__device__ float    g_ht1[EE_MAX * H64 + 256];
__device__ uint32_t g_w2bh0[33 * 2176];     // fp16x2 packed B chunk64s, layer 0
__device__ uint32_t g_w2bh1[66 * 2176];     // fp16x2 packed B chunk64s, layer 1
__device__ float    g_agg0[NN_MAX * H64];
__device__ float    g_agg1[NN_MAX * H64];

// ---------------- PTX helpers ------------------------------------------------
__device__ __forceinline__ uint32_t smem_u32(const void* p) {
    return (uint32_t)__cvta_generic_to_shared(p);
}
__device__ __forceinline__ void cp_async16(uint32_t s, const void* g) {
    asm volatile("cp.async.cg.shared.global [%0], [%1], 16;" :: "r"(s), "l"(g));
}
#define CP_COMMIT() asm volatile("cp.async.commit_group;" ::: "memory")
#define CP_WAIT1()  asm volatile("cp.async.wait_group 1;" ::: "memory")

// pack {lo=v0, hi=v1} as fp16x2
__device__ __forceinline__ uint32_t packf16(float v0, float v1) {
    uint32_t d;
    asm("cvt.rn.f16x2.f32 %0, %1, %2;" : "=r"(d) : "f"(v1), "f"(v0));
    return d;
}

__device__ __forceinline__ void mma_f16(float* d, uint32_t a0, uint32_t a1,
                                        uint32_t a2, uint32_t a3,
                                        uint32_t b0, uint32_t b1) {
    asm volatile(
        "mma.sync.aligned.m16n8k16.row.col.f32.f16.f16.f32 "
        "{%0,%1,%2,%3}, {%4,%5,%6,%7}, {%8,%9}, {%0,%1,%2,%3};"
        : "+f"(d[0]), "+f"(d[1]), "+f"(d[2]), "+f"(d[3])
        : "r"(a0), "r"(a1), "r"(a2), "r"(a3), "r"(b0), "r"(b1));
}

// ---------------- kernel 1: both edge MLPs, h^T stored [j][e] ---------------
__global__ void edge_mlp_both_kernel(const float* __restrict__ ea,
                                     const float* __restrict__ w1_0,
                                     const float* __restrict__ b1_0,
                                     const float* __restrict__ w1_1,
                                     const float* __restrict__ b1_1,
                                     float* __restrict__ ht0,
                                     float* __restrict__ ht1, int E)
{
    int e = blockIdx.x * blockDim.x + threadIdx.x;
    int j = blockIdx.y;
    if (e >= E) return;
    float a0 = __ldg(&ea[2 * e]);
    float a1 = __ldg(&ea[2 * e + 1]);
    const float* w1 = blockIdx.z ? w1_1 : w1_0;
    const float* b1 = blockIdx.z ? b1_1 : b1_0;
    float* ht       = blockIdx.z ? ht1  : ht0;
    float v = fmaf(a0, __ldg(&w1[j]), fmaf(a1, __ldg(&w1[H64 + j]), __ldg(&b1[j])));
    ht[(size_t)j * E + e] = fmaxf(v, 0.0f);
}

// ---------------- kernel 2: pack fp16 B chunk64 tables ----------------------
// chunk64 c: 16 rows (row = s*4 + t; s = k16-step 0..3), 64 cols n, pair p.
//   fp16x2 word = { B[kap(k0)][n], B[kap(k0+1)][n] },  k0 = 2t + 8p (kappa)
//   network k = 2c' + (s>>1);  i = ihalf*32 + (s&1)*16 + kappa
// word offset in chunk: row*136 + n*2 + p (row stride 136 words = 544 B)
__global__ void prep_both_kernel(const float* __restrict__ w2_0,
                                 const float* __restrict__ b2_0,
                                 const float* __restrict__ w2_1,
                                 const float* __restrict__ b2_1)
{
    int idx = blockIdx.x * blockDim.x + threadIdx.x;
    if (idx >= 66 * 2048) return;
    int c = idx >> 11, rem = idx & 2047;
    int row = rem >> 7;            // 0..15
    int n   = (rem >> 1) & 63;
    int p   = rem & 1;
    int s = row >> 2, t = row & 3;
    int k0 = 2 * t + 8 * p;        // kappa for u=0; u=1 is k0+1
    int word = row * 136 + n * 2 + p;

    if (c < 33) {       // layer 0 (ih = 0)
        float v0 = 0.f, v1 = 0.f;
        if (c < 32) {
            int k = 2 * c + (s >> 1);
            int i = (s & 1) * 16 + k0;
            v0 = w2_0[k * 2048 + i * H64 + n];
            v1 = w2_0[k * 2048 + (i + 1) * H64 + n];
        } else if (s < 2) {
            int i = s * 16 + k0;
            v0 = b2_0[i * H64 + n];
            v1 = b2_0[(i + 1) * H64 + n];
        }
        g_w2bh0[c * 2176 + word] = packf16(v0, v1);
    }
    {                   // layer 1
        int ih = (c >= 33) ? 1 : 0;
        int cc = c - 33 * ih;
        float v0 = 0.f, v1 = 0.f;
        if (cc < 32) {
            int k = 2 * cc + (s >> 1);
            int i = ih * 32 + (s & 1) * 16 + k0;
            v0 = w2_1[k * 4096 + i * H64 + n];
            v1 = w2_1[k * 4096 + (i + 1) * H64 + n];
        } else if (s < 2) {
            int i = ih * 32 + s * 16 + k0;
            v0 = b2_1[i * H64 + n];
            v1 = b2_1[(i + 1) * H64 + n];
        }
        g_w2bh1[c * 2176 + word] = packf16(v0, v1);
    }
}

// ---------------- kernel 3: agg = (relu?)x @ root + bias --------------------
template<int IN_C, bool RELU_IN>
__global__ void root_init_kernel(const float* __restrict__ x,
                                 const float* __restrict__ root,
                                 const float* __restrict__ bias,
                                 float* __restrict__ agg)
{
    __shared__ float xr[IN_C];
    int n = blockIdx.x, t = threadIdx.x;
    if (t < IN_C) {
        float v = x[n * IN_C + t];
        xr[t] = RELU_IN ? fmaxf(v, 0.0f) : v;
    }
    __syncthreads();
    float v = __ldg(&bias[t]);
    #pragma unroll
    for (int i = 0; i < IN_C; i++)
        v = fmaf(xr[i], __ldg(&root[i * H64 + t]), v);
    agg[n * H64 + t] = v;
}

// ---------------- kernel 4: fused msg GEMM (mma.sync fp16) + scatter --------
// CTA = 128 edges x 64 outs, 4 warps; warp tile 32 rows x 64 cols
// (2 mtiles share every B fragment -> B L2 traffic halved vs 64-edge CTAs).
// K-chunks of 64 (2 network-k x 32 i), triple-buffered cp.async for B + h.
template<int IN_C, bool RELU_IN>
__global__ void __launch_bounds__(128, 3)
fused_mma_kernel(const float* __restrict__ x, const int* __restrict__ ei, int E,
                 const float* __restrict__ ht, const uint32_t* __restrict__ w2b,
                 float* __restrict__ agg)
{
    constexpr int NCHUNK = (IN_C == 32) ? 33 : 66;
    constexpr int XROW   = IN_C + 4;
    constexpr int B_OFF  = 0;                 // 3 x 8704
    constexpr int H_OFF  = 26112;             // 3 x 1024 ([slot][kk 0..1][e 0..127])
    constexpr int X_OFF  = 29184;
    constexpr int DST_OFF = X_OFF + 128 * XROW * 4;

    extern __shared__ char smem[];
    float* x_s   = (float*)(smem + X_OFF);
    float* h_s   = (float*)(smem + H_OFF);
    int*   dst_s = (int*)(smem + DST_OFF);
    uint32_t sbase = smem_u32(smem);

    int tid = threadIdx.x;
    int e0  = blockIdx.x * 128;

    // ---- gather x[src] tile (relu on read for layer 1) ----
    constexpr int XV = IN_C / 4;
    for (int q = tid; q < 128 * XV; q += 128) {
        int e = q / XV, cc = q % XV;
        int ge = e0 + e;
        int s = (ge < E) ? ei[ge] : 0;
        float4 v = *(const float4*)(x + (size_t)s * IN_C + cc * 4);
        if (RELU_IN) {
            v.x = fmaxf(v.x, 0.0f); v.y = fmaxf(v.y, 0.0f);
            v.z = fmaxf(v.z, 0.0f); v.w = fmaxf(v.w, 0.0f);
        }
        *(float4*)&x_s[e * XROW + cc * 4] = v;
    }
    dst_s[tid] = (e0 + tid < E) ? ei[E + e0 + tid] : -1;

    // ---- prefetch: B chunk (8704 B) + 2 h columns (1024 B) ----
    auto prefetch = [&](int c) {
        if (c < NCHUNK) {
            int slot = c % 3;
            uint32_t bs = sbase + B_OFF + slot * 8704;
            const char* g = (const char*)w2b + (size_t)c * 8704;
            #pragma unroll
            for (int o = 0; o < 8192; o += 2048)
                cp_async16(bs + o + tid * 16, g + o + tid * 16);
            if (tid < 32) cp_async16(bs + 8192 + tid * 16, g + 8192 + tid * 16);
            bool isBias = (IN_C == 32) ? (c == 32) : (c == 32 || c == 65);
            if (!isBias && tid < 64) {
                int cc = (IN_C == 32) ? c : ((c < 33) ? c : c - 33);
                int kk = tid >> 5, ln = tid & 31;
                cp_async16(sbase + H_OFF + slot * 1024 + kk * 512 + ln * 16,
                           ht + (size_t)(2 * cc + kk) * E + e0 + ln * 4);
            }
        }
        CP_COMMIT();
    };
    prefetch(0);
    prefetch(1);
    __syncthreads();   // x_s / dst_s visible

    const int w    = tid >> 5;
    const int lane = tid & 31;
    const int gid  = lane >> 2;
    const int tig  = lane & 3;

    int rows[4];                       // warp rows: w*32 + j*8 + gid
    #pragma unroll
    for (int j = 0; j < 4; j++) rows[j] = w * 32 + j * 8 + gid;

    // xreg[r][j], j = m*4 + p*2 + u -> i = ih + m*16 + 2*tig + 8*p + u
    float xreg[4][8];
    auto load_xreg = [&](int ih) {
        #pragma unroll
        for (int r = 0; r < 4; r++)
            #pragma unroll
            for (int j = 0; j < 8; j++)
                xreg[r][j] = x_s[rows[r] * XROW + ih +
                                 (j >> 2) * 16 + 2 * tig + 8 * ((j >> 1) & 1) + (j & 1)];
    };
    load_xreg(0);

    float acc[2][8][4];
    #pragma unroll
    for (int mt = 0; mt < 2; mt++)
        #pragma unroll
        for (int q = 0; q < 8; q++)
            #pragma unroll
            for (int u = 0; u < 4; u++) acc[mt][q][u] = 0.0f;

    for (int c = 0; c < NCHUNK; c++) {
        if (IN_C == 64 && c == 33) load_xreg(32);   // switch to i-half 1
        CP_WAIT1();
        __syncthreads();                  // chunk c resident; slot (c+2)%3 free
        prefetch(c + 2);

        int slot = c % 3;
        bool isBias = (IN_C == 32) ? (c == 32) : (c == 32 || c == 65);
        float hk[2][4];                   // [kk][row j]
        if (isBias) {
            #pragma unroll
            for (int j = 0; j < 4; j++) { hk[0][j] = 1.0f; hk[1][j] = 1.0f; }
        } else {
            const float* hb = h_s + slot * 256;
            #pragma unroll
            for (int j = 0; j < 4; j++) {
                hk[0][j] = hb[rows[j]];
                hk[1][j] = hb[128 + rows[j]];
            }
        }

        uint32_t bbase = sbase + B_OFF + slot * 8704;
        #pragma unroll
        for (int s = 0; s < 4; s++) {
            int kk = s >> 1, jb = (s & 1) * 4;
            uint32_t a[2][4];
            #pragma unroll
            for (int mt = 0; mt < 2; mt++) {
                float h0 = hk[kk][mt * 2], h1 = hk[kk][mt * 2 + 1];
                const float* x0 = xreg[mt * 2];
                const float* x1 = xreg[mt * 2 + 1];
                a[mt][0] = packf16(h0 * x0[jb + 0], h0 * x0[jb + 1]);
                a[mt][1] = packf16(h1 * x1[jb + 0], h1 * x1[jb + 1]);
                a[mt][2] = packf16(h0 * x0[jb + 2], h0 * x0[jb + 3]);
                a[mt][3] = packf16(h1 * x1[jb + 2], h1 * x1[jb + 3]);
            }
            uint32_t brow = bbase + (uint32_t)(s * 4 + tig) * 544 + (uint32_t)gid * 8;
            #pragma unroll
            for (int q = 0; q < 8; q++) {
                uint32_t b0, b1;
                asm volatile("ld.shared.v2.b32 {%0, %1}, [%2];"
                             : "=r"(b0), "=r"(b1) : "r"(brow + q * 64));
                mma_f16(acc[0][q], a[0][0], a[0][1], a[0][2], a[0][3], b0, b1);
                mma_f16(acc[1][q], a[1][0], a[1][1], a[1][2], a[1][3], b0, b1);
            }
        }
    }

    // ---- scatter-add into agg[dst] ----
    #pragma unroll
    for (int mt = 0; mt < 2; mt++) {
        int d0 = dst_s[rows[mt * 2]];
        int d1 = dst_s[rows[mt * 2 + 1]];
        float* p0 = agg + (size_t)(d0 < 0 ? 0 : d0) * H64;
        float* p1 = agg + (size_t)(d1 < 0 ? 0 : d1) * H64;
        #pragma unroll
        for (int q = 0; q < 8; q++) {
            int n = q * 8 + tig * 2;
            if (d0 >= 0) {
                atomicAdd(p0 + n,     acc[mt][q][0]);
                atomicAdd(p0 + n + 1, acc[mt][q][1]);
            }
            if (d1 >= 0) {
                atomicAdd(p1 + n,     acc[mt][q][2]);
                atomicAdd(p1 + n + 1, acc[mt][q][3]);
            }
        }
    }
}

// ---------------- kernel 5: out = relu(agg1) --------------------------------
__global__ void relu_out_kernel(const float* __restrict__ in,
                                float* __restrict__ out, int n)
{
    int i = blockIdx.x * blockDim.x + threadIdx.x;
    if (i < n) out[i] = fmaxf(in[i], 0.0f);
}

// ---------------- launch -----------------------------------------------------
extern "C" void kernel_launch(void* const* d_in, const int* in_sizes, int n_in,
                              void* d_out, int out_size)
{
    const float* x      = (const float*)d_in[0];
    const int*   ei     = (const int*)  d_in[1];
    const float* ea     = (const float*)d_in[2];
    const float* w1_0   = (const float*)d_in[3];
    const float* b1_0   = (const float*)d_in[4];
    const float* w2_0   = (const float*)d_in[5];
    const float* b2_0   = (const float*)d_in[6];
    const float* root_0 = (const float*)d_in[7];
    const float* bias_0 = (const float*)d_in[8];
    const float* w1_1   = (const float*)d_in[9];
    const float* b1_1   = (const float*)d_in[10];
    const float* w2_1   = (const float*)d_in[11];
    const float* b2_1   = (const float*)d_in[12];
    const float* root_1 = (const float*)d_in[13];
    const float* bias_1 = (const float*)d_in[14];

    const int N = in_sizes[0] / 32;   // 20000
    const int E = in_sizes[1] / 2;    // 50000

    void* p;
    cudaGetSymbolAddress(&p, g_ht0);   float* ht0  = (float*)p;
    cudaGetSymbolAddress(&p, g_ht1);   float* ht1  = (float*)p;
    cudaGetSymbolAddress(&p, g_w2bh0); uint32_t* w2b0 = (uint32_t*)p;
    cudaGetSymbolAddress(&p, g_w2bh1); uint32_t* w2b1 = (uint32_t*)p;
    cudaGetSymbolAddress(&p, g_agg0);  float* agg0 = (float*)p;
    cudaGetSymbolAddress(&p, g_agg1);  float* agg1 = (float*)p;

    const int smem0 = 29184 + 128 * 36 * 4 + 512;   // 48128
    const int smem1 = 29184 + 128 * 68 * 4 + 512;   // 64512
    cudaFuncSetAttribute(fused_mma_kernel<32, false>,
                         cudaFuncAttributeMaxDynamicSharedMemorySize, smem0);
    cudaFuncSetAttribute(fused_mma_kernel<64, true>,
                         cudaFuncAttributeMaxDynamicSharedMemorySize, smem1);

    const int threads = 256;
    dim3 grid_h((E + threads - 1) / threads, H64, 2);
    const int grid_fuse = (E + 127) / 128;
    const int grid_relu = (N * H64 + threads - 1) / threads;

    edge_mlp_both_kernel<<<grid_h, threads>>>(ea, w1_0, b1_0, w1_1, b1_1, ht0, ht1, E);
    prep_both_kernel<<<(66 * 2048 + threads - 1) / threads, threads>>>(w2_0, b2_0, w2_1, b2_1);

    // layer 0
    root_init_kernel<32, false><<<N, H64>>>(x, root_0, bias_0, agg0);
    fused_mma_kernel<32, false><<<grid_fuse, 128, smem0>>>(x, ei, E, ht0, w2b0, agg0);

    // layer 1 (relu fused into readers)
    root_init_kernel<64, true><<<N, H64>>>(agg0, root_1, bias_1, agg1);
    fused_mma_kernel<64, true><<<grid_fuse, 128, smem1>>>(agg0, ei, E, ht1, w2b1, agg1);

    relu_out_kernel<<<grid_relu, threads>>>(agg1, (float*)d_out, N * H64);
}

// round 9
// speedup vs baseline: 2.1037x; 1.1676x over previous
#include <cuda_runtime.h>
#include <cuda_fp16.h>
#include <cstdint>

#define H64 64
#define EE_MAX 50000
#define NN_MAX 20000

// ---------------- scratch (static device globals) ---------------------------
__device__ __half   g_ht0[EE_MAX * H64 + 256];  // edge MLP out, fp16, [j][e]
__device__ __half   g_ht1[EE_MAX * H64 + 256];
__device__ uint32_t g_w2bh0[33 * 2176];         // fp16x2 packed B chunk64s, L0
__device__ uint32_t g_w2bh1[66 * 2176];         // fp16x2 packed B chunk64s, L1
__device__ float    g_agg0[NN_MAX * H64];
__device__ float    g_agg1[NN_MAX * H64];

// ---------------- PTX helpers ------------------------------------------------
__device__ __forceinline__ uint32_t smem_u32(const void* p) {
    return (uint32_t)__cvta_generic_to_shared(p);
}
__device__ __forceinline__ void cp_async16(uint32_t s, const void* g) {
    asm volatile("cp.async.cg.shared.global [%0], [%1], 16;" :: "r"(s), "l"(g));
}
#define CP_COMMIT() asm volatile("cp.async.commit_group;" ::: "memory")
#define CP_WAIT1()  asm volatile("cp.async.wait_group 1;" ::: "memory")

__device__ __forceinline__ uint32_t packf16(float v0, float v1) {
    uint32_t d;
    asm("cvt.rn.f16x2.f32 %0, %1, %2;" : "=r"(d) : "f"(v1), "f"(v0));
    return d;
}

__device__ __forceinline__ void mma_f16(float* d, uint32_t a0, uint32_t a1,
                                        uint32_t a2, uint32_t a3,
                                        uint32_t b0, uint32_t b1) {
    asm volatile(
        "mma.sync.aligned.m16n8k16.row.col.f32.f16.f16.f32 "
        "{%0,%1,%2,%3}, {%4,%5,%6,%7}, {%8,%9}, {%0,%1,%2,%3};"
        : "+f"(d[0]), "+f"(d[1]), "+f"(d[2]), "+f"(d[3])
        : "r"(a0), "r"(a1), "r"(a2), "r"(a3), "r"(b0), "r"(b1));
}

// ---------------- kernel A: setup mega-kernel -------------------------------
// flat 1D grid, 256 threads; segments:
//   [0, nb_mlp)            : both edge MLPs, h^T fp16 stored [j][e]
//   [nb_mlp, +528)         : pack both fp16 B chunk64 tables
//   [.., +N*64/256)        : root0 direct write into agg0; zero agg1
__global__ void __launch_bounds__(256)
setup_kernel(const float* __restrict__ ea,
             const float* __restrict__ w1_0, const float* __restrict__ b1_0,
             const float* __restrict__ w1_1, const float* __restrict__ b1_1,
             const float* __restrict__ w2_0, const float* __restrict__ b2_0,
             const float* __restrict__ w2_1, const float* __restrict__ b2_1,
             const float* __restrict__ x,
             const float* __restrict__ root_0, const float* __restrict__ bias_0,
             int E, int N, int ebpj, int nb_mlp, int nb_prep)
{
    int b = blockIdx.x, tid = threadIdx.x;

    if (b < nb_mlp) {
        // ---- edge MLP (both layers per thread) ----
        int j = b / ebpj, eb = b % ebpj;
        int e = eb * 256 + tid;
        if (e >= E) return;
        float a0 = __ldg(&ea[2 * e]);
        float a1 = __ldg(&ea[2 * e + 1]);
        float v0 = fmaf(a0, __ldg(&w1_0[j]), fmaf(a1, __ldg(&w1_0[H64 + j]), __ldg(&b1_0[j])));
        float v1 = fmaf(a0, __ldg(&w1_1[j]), fmaf(a1, __ldg(&w1_1[H64 + j]), __ldg(&b1_1[j])));
        g_ht0[(size_t)j * E + e] = __float2half(fmaxf(v0, 0.0f));
        g_ht1[(size_t)j * E + e] = __float2half(fmaxf(v1, 0.0f));
        return;
    }
    if (b < nb_mlp + nb_prep) {
        // ---- pack B chunk64 tables (pair layout) ----
        int idx = (b - nb_mlp) * 256 + tid;          // < 66*2048
        int c = idx >> 11, rem = idx & 2047;
        int row = rem >> 7;
        int n   = (rem >> 1) & 63;
        int p   = rem & 1;
        int s = row >> 2, t = row & 3;
        int k0 = 2 * t + 8 * p;
        int word = row * 136 + n * 2 + p;

        if (c < 33) {       // layer 0
            float v0 = 0.f, v1 = 0.f;
            if (c < 32) {
                int k = 2 * c + (s >> 1);
                int i = (s & 1) * 16 + k0;
                v0 = w2_0[k * 2048 + i * H64 + n];
                v1 = w2_0[k * 2048 + (i + 1) * H64 + n];
            } else if (s < 2) {
                int i = s * 16 + k0;
                v0 = b2_0[i * H64 + n];
                v1 = b2_0[(i + 1) * H64 + n];
            }
            g_w2bh0[c * 2176 + word] = packf16(v0, v1);
        }
        {                   // layer 1
            int ih = (c >= 33) ? 1 : 0;
            int cc = c - 33 * ih;
            float v0 = 0.f, v1 = 0.f;
            if (cc < 32) {
                int k = 2 * cc + (s >> 1);
                int i = ih * 32 + (s & 1) * 16 + k0;
                v0 = w2_1[k * 4096 + i * H64 + n];
                v1 = w2_1[k * 4096 + (i + 1) * H64 + n];
            } else if (s < 2) {
                int i = ih * 32 + s * 16 + k0;
                v0 = b2_1[i * H64 + n];
                v1 = b2_1[(i + 1) * H64 + n];
            }
            g_w2bh1[c * 2176 + word] = packf16(v0, v1);
        }
        return;
    }
    // ---- root0: agg0 = x @ root_0 + bias_0 ; agg1 = 0 ----
    int idx = (b - nb_mlp - nb_prep) * 256 + tid;
    if (idx >= N * H64) return;
    int n = idx >> 6, t = idx & 63;
    float v = __ldg(&bias_0[t]);
    const float* xr = x + (size_t)n * 32;
    #pragma unroll
    for (int i = 0; i < 32; i++)
        v = fmaf(__ldg(&xr[i]), __ldg(&root_0[i * H64 + t]), v);
    g_agg0[idx] = v;
    g_agg1[idx] = 0.0f;
}

// ---------------- fused msg GEMM (mma.sync fp16) + scatter [+ root backfill]
// blocks [0, gridFuse): CTA = 128 edges x 64 outs, 4 warps (32x64 warp tile),
//   K-chunks of 64, triple-buffered cp.async for B + h(fp16).
// blocks >= gridFuse (layer 1 only): root1 term, thread-per-output
//   grid-stride, atomicAdd into agg (agg pre-zeroed in setup).
template<int IN_C, bool RELU_IN>
__global__ void __launch_bounds__(128, 3)
fused_mma_kernel(const float* __restrict__ x, const int* __restrict__ ei, int E,
                 const __half* __restrict__ ht, const uint32_t* __restrict__ w2b,
                 float* __restrict__ agg,
                 const float* __restrict__ rootW, const float* __restrict__ rootB,
                 int N, int gridFuse, int rootBlocks)
{
    constexpr int NCHUNK = (IN_C == 32) ? 33 : 66;
    constexpr int XROW   = IN_C + 4;
    constexpr int B_OFF  = 0;                 // 3 x 8704
    constexpr int H_OFF  = 26112;             // 3 x 512 ([slot][kk][e], fp16)
    constexpr int X_OFF  = 27648;
    constexpr int DST_OFF = X_OFF + 128 * XROW * 4;

    int tid = threadIdx.x;

    if (blockIdx.x >= (unsigned)gridFuse) {
        // ---- root backfill path (no smem, no syncs) ----
        int stride = rootBlocks * 128;
        for (int idx = (blockIdx.x - gridFuse) * 128 + tid; idx < N * H64; idx += stride) {
            int n = idx >> 6, t = idx & 63;
            float v = __ldg(&rootB[t]);
            const float* xr = x + (size_t)n * H64;
            #pragma unroll
            for (int i = 0; i < H64; i++)
                v = fmaf(fmaxf(__ldg(&xr[i]), 0.0f), __ldg(&rootW[i * H64 + t]), v);
            atomicAdd(&agg[idx], v);
        }
        return;
    }

    extern __shared__ char smem[];
    float* x_s   = (float*)(smem + X_OFF);
    int*   dst_s = (int*)(smem + DST_OFF);
    uint32_t sbase = smem_u32(smem);

    int e0 = blockIdx.x * 128;

    // ---- gather x[src] tile (relu on read for layer 1) ----
    constexpr int XV = IN_C / 4;
    for (int q = tid; q < 128 * XV; q += 128) {
        int e = q / XV, cc = q % XV;
        int ge = e0 + e;
        int s = (ge < E) ? ei[ge] : 0;
        float4 v = *(const float4*)(x + (size_t)s * IN_C + cc * 4);
        if (RELU_IN) {
            v.x = fmaxf(v.x, 0.0f); v.y = fmaxf(v.y, 0.0f);
            v.z = fmaxf(v.z, 0.0f); v.w = fmaxf(v.w, 0.0f);
        }
        *(float4*)&x_s[e * XROW + cc * 4] = v;
    }
    dst_s[tid] = (e0 + tid < E) ? ei[E + e0 + tid] : -1;

    // ---- prefetch: B chunk (8704 B) + 2 h columns (512 B fp16) ----
    auto prefetch = [&](int c) {
        if (c < NCHUNK) {
            int slot = c % 3;
            uint32_t bs = sbase + B_OFF + slot * 8704;
            const char* g = (const char*)w2b + (size_t)c * 8704;
            #pragma unroll
            for (int o = 0; o < 8192; o += 2048)
                cp_async16(bs + o + tid * 16, g + o + tid * 16);
            if (tid < 32) cp_async16(bs + 8192 + tid * 16, g + 8192 + tid * 16);
            bool isBias = (IN_C == 32) ? (c == 32) : (c == 32 || c == 65);
            if (!isBias && tid < 32) {
                int cc = (IN_C == 32) ? c : ((c < 33) ? c : c - 33);
                int kk = tid >> 4, ln = tid & 15;
                cp_async16(sbase + H_OFF + slot * 512 + kk * 256 + ln * 16,
                           ht + (size_t)(2 * cc + kk) * E + e0 + ln * 8);
            }
        }
        CP_COMMIT();
    };
    prefetch(0);
    prefetch(1);
    __syncthreads();   // x_s / dst_s visible

    const int w    = tid >> 5;
    const int lane = tid & 31;
    const int gid  = lane >> 2;
    const int tig  = lane & 3;

    int rows[4];
    #pragma unroll
    for (int j = 0; j < 4; j++) rows[j] = w * 32 + j * 8 + gid;

    float xreg[4][8];
    auto load_xreg = [&](int ih) {
        #pragma unroll
        for (int r = 0; r < 4; r++)
            #pragma unroll
            for (int j = 0; j < 8; j++)
                xreg[r][j] = x_s[rows[r] * XROW + ih +
                                 (j >> 2) * 16 + 2 * tig + 8 * ((j >> 1) & 1) + (j & 1)];
    };
    load_xreg(0);

    float acc[2][8][4];
    #pragma unroll
    for (int mt = 0; mt < 2; mt++)
        #pragma unroll
        for (int q = 0; q < 8; q++)
            #pragma unroll
            for (int u = 0; u < 4; u++) acc[mt][q][u] = 0.0f;

    for (int c = 0; c < NCHUNK; c++) {
        if (IN_C == 64 && c == 33) load_xreg(32);
        CP_WAIT1();
        __syncthreads();
        prefetch(c + 2);

        int slot = c % 3;
        bool isBias = (IN_C == 32) ? (c == 32) : (c == 32 || c == 65);
        float hk[2][4];
        if (isBias) {
            #pragma unroll
            for (int j = 0; j < 4; j++) { hk[0][j] = 1.0f; hk[1][j] = 1.0f; }
        } else {
            const __half* hb = (const __half*)(smem + H_OFF + slot * 512);
            #pragma unroll
            for (int j = 0; j < 4; j++) {
                hk[0][j] = __half2float(hb[rows[j]]);
                hk[1][j] = __half2float(hb[128 + rows[j]]);
            }
        }

        uint32_t bbase = sbase + B_OFF + slot * 8704;
        #pragma unroll
        for (int s = 0; s < 4; s++) {
            int kk = s >> 1, jb = (s & 1) * 4;
            uint32_t a[2][4];
            #pragma unroll
            for (int mt = 0; mt < 2; mt++) {
                float h0 = hk[kk][mt * 2], h1 = hk[kk][mt * 2 + 1];
                const float* x0 = xreg[mt * 2];
                const float* x1 = xreg[mt * 2 + 1];
                a[mt][0] = packf16(h0 * x0[jb + 0], h0 * x0[jb + 1]);
                a[mt][1] = packf16(h1 * x1[jb + 0], h1 * x1[jb + 1]);
                a[mt][2] = packf16(h0 * x0[jb + 2], h0 * x0[jb + 3]);
                a[mt][3] = packf16(h1 * x1[jb + 2], h1 * x1[jb + 3]);
            }
            uint32_t brow = bbase + (uint32_t)(s * 4 + tig) * 544 + (uint32_t)gid * 8;
            #pragma unroll
            for (int q = 0; q < 8; q++) {
                uint32_t b0, b1;
                asm volatile("ld.shared.v2.b32 {%0, %1}, [%2];"
                             : "=r"(b0), "=r"(b1) : "r"(brow + q * 64));
                mma_f16(acc[0][q], a[0][0], a[0][1], a[0][2], a[0][3], b0, b1);
                mma_f16(acc[1][q], a[1][0], a[1][1], a[1][2], a[1][3], b0, b1);
            }
        }
    }

    // ---- scatter-add into agg[dst] ----
    #pragma unroll
    for (int mt = 0; mt < 2; mt++) {
        int d0 = dst_s[rows[mt * 2]];
        int d1 = dst_s[rows[mt * 2 + 1]];
        float* p0 = agg + (size_t)(d0 < 0 ? 0 : d0) * H64;
        float* p1 = agg + (size_t)(d1 < 0 ? 0 : d1) * H64;
        #pragma unroll
        for (int q = 0; q < 8; q++) {
            int n = q * 8 + tig * 2;
            if (d0 >= 0) {
                atomicAdd(p0 + n,     acc[mt][q][0]);
                atomicAdd(p0 + n + 1, acc[mt][q][1]);
            }
            if (d1 >= 0) {
                atomicAdd(p1 + n,     acc[mt][q][2]);
                atomicAdd(p1 + n + 1, acc[mt][q][3]);
            }
        }
    }
}

// ---------------- relu out ----------------------------------------------------
__global__ void relu_out_kernel(const float* __restrict__ in,
                                float* __restrict__ out, int n)
{
    int i = blockIdx.x * blockDim.x + threadIdx.x;
    if (i < n) out[i] = fmaxf(in[i], 0.0f);
}

// ---------------- launch -----------------------------------------------------
extern "C" void kernel_launch(void* const* d_in, const int* in_sizes, int n_in,
                              void* d_out, int out_size)
{
    const float* x      = (const float*)d_in[0];
    const int*   ei     = (const int*)  d_in[1];
    const float* ea     = (const float*)d_in[2];
    const float* w1_0   = (const float*)d_in[3];
    const float* b1_0   = (const float*)d_in[4];
    const float* w2_0   = (const float*)d_in[5];
    const float* b2_0   = (const float*)d_in[6];
    const float* root_0 = (const float*)d_in[7];
    const float* bias_0 = (const float*)d_in[8];
    const float* w1_1   = (const float*)d_in[9];
    const float* b1_1   = (const float*)d_in[10];
    const float* w2_1   = (const float*)d_in[11];
    const float* b2_1   = (const float*)d_in[12];
    const float* root_1 = (const float*)d_in[13];
    const float* bias_1 = (const float*)d_in[14];

    const int N = in_sizes[0] / 32;   // 20000
    const int E = in_sizes[1] / 2;    // 50000

    void* p;
    cudaGetSymbolAddress(&p, g_ht0);   __half* ht0 = (__half*)p;
    cudaGetSymbolAddress(&p, g_ht1);   __half* ht1 = (__half*)p;
    cudaGetSymbolAddress(&p, g_w2bh0); uint32_t* w2b0 = (uint32_t*)p;
    cudaGetSymbolAddress(&p, g_w2bh1); uint32_t* w2b1 = (uint32_t*)p;
    cudaGetSymbolAddress(&p, g_agg0);  float* agg0 = (float*)p;
    cudaGetSymbolAddress(&p, g_agg1);  float* agg1 = (float*)p;

    const int smem0 = 27648 + 128 * 36 * 4 + 512;   // 46592
    const int smem1 = 27648 + 128 * 68 * 4 + 512;   // 62976
    cudaFuncSetAttribute(fused_mma_kernel<32, false>,
                         cudaFuncAttributeMaxDynamicSharedMemorySize, smem0);
    cudaFuncSetAttribute(fused_mma_kernel<64, true>,
                         cudaFuncAttributeMaxDynamicSharedMemorySize, smem1);

    // ---- launch A: setup mega-kernel ----
    const int ebpj    = (E + 255) / 256;
    const int nb_mlp  = ebpj * H64;
    const int nb_prep = (66 * 2048) / 256;          // 528
    const int nb_root = (N * H64 + 255) / 256;
    setup_kernel<<<nb_mlp + nb_prep + nb_root, 256>>>(
        ea, w1_0, b1_0, w1_1, b1_1, w2_0, b2_0, w2_1, b2_1,
        x, root_0, bias_0, E, N, ebpj, nb_mlp, nb_prep);

    const int grid_fuse = (E + 127) / 128;
    const int ROOT_BLKS = 592;

    // ---- launch B: fused layer 0 (no root backfill) ----
    fused_mma_kernel<32, false><<<grid_fuse, 128, smem0>>>(
        x, ei, E, ht0, w2b0, agg0, nullptr, nullptr, N, grid_fuse, 0);

    // ---- launch C: fused layer 1 + root1 backfill ----
    fused_mma_kernel<64, true><<<grid_fuse + ROOT_BLKS, 128, smem1>>>(
        agg0, ei, E, ht1, w2b1, agg1, root_1, bias_1, N, grid_fuse, ROOT_BLKS);

    // ---- launch D: relu out ----
    relu_out_kernel<<<(N * H64 + 255) / 256, 256>>>(agg1, (float*)d_out, N * H64);
}

// round 10
// speedup vs baseline: 2.1457x; 1.0200x over previous
#include <cuda_runtime.h>
#include <cuda_fp16.h>
#include <cstdint>

#define H64 64
#define EE_MAX 50000
#define NN_MAX 20000

// ---------------- scratch (static device globals) ---------------------------
__device__ __half   g_ht0[EE_MAX * H64 + 256];  // edge MLP out, fp16, [j][e]
__device__ __half   g_ht1[EE_MAX * H64 + 256];
__device__ uint32_t g_w2bh0[33 * 2176];         // fp16x2 packed B chunk64s, L0
__device__ uint32_t g_w2bh1[66 * 2176];         // fp16x2 packed B chunk64s, L1
__device__ float    g_agg0[NN_MAX * H64];
__device__ float    g_agg1[NN_MAX * H64];

// ---------------- PTX helpers ------------------------------------------------
__device__ __forceinline__ uint32_t smem_u32(const void* p) {
    return (uint32_t)__cvta_generic_to_shared(p);
}
__device__ __forceinline__ void cp_async16(uint32_t s, const void* g) {
    asm volatile("cp.async.cg.shared.global [%0], [%1], 16;" :: "r"(s), "l"(g));
}
#define CP_COMMIT() asm volatile("cp.async.commit_group;" ::: "memory")
#define CP_WAIT1()  asm volatile("cp.async.wait_group 1;" ::: "memory")
#define GDC_WAIT()  asm volatile("griddepcontrol.wait;" ::: "memory")

__device__ __forceinline__ uint32_t packf16(float v0, float v1) {
    uint32_t d;
    asm("cvt.rn.f16x2.f32 %0, %1, %2;" : "=r"(d) : "f"(v1), "f"(v0));
    return d;
}

__device__ __forceinline__ void mma_f16(float* d, uint32_t a0, uint32_t a1,
                                        uint32_t a2, uint32_t a3,
                                        uint32_t b0, uint32_t b1) {
    asm volatile(
        "mma.sync.aligned.m16n8k16.row.col.f32.f16.f16.f32 "
        "{%0,%1,%2,%3}, {%4,%5,%6,%7}, {%8,%9}, {%0,%1,%2,%3};"
        : "+f"(d[0]), "+f"(d[1]), "+f"(d[2]), "+f"(d[3])
        : "r"(a0), "r"(a1), "r"(a2), "r"(a3), "r"(b0), "r"(b1));
}

// ---------------- kernel A: setup mega-kernel -------------------------------
__global__ void __launch_bounds__(256)
setup_kernel(const float* __restrict__ ea,
             const float* __restrict__ w1_0, const float* __restrict__ b1_0,
             const float* __restrict__ w1_1, const float* __restrict__ b1_1,
             const float* __restrict__ w2_0, const float* __restrict__ b2_0,
             const float* __restrict__ w2_1, const float* __restrict__ b2_1,
             const float* __restrict__ x,
             const float* __restrict__ root_0, const float* __restrict__ bias_0,
             int E, int N, int ebpj, int nb_mlp, int nb_prep)
{
    int b = blockIdx.x, tid = threadIdx.x;

    if (b < nb_mlp) {
        // ---- edge MLP (both layers per thread) ----
        int j = b / ebpj, eb = b % ebpj;
        int e = eb * 256 + tid;
        if (e >= E) return;
        float a0 = __ldg(&ea[2 * e]);
        float a1 = __ldg(&ea[2 * e + 1]);
        float v0 = fmaf(a0, __ldg(&w1_0[j]), fmaf(a1, __ldg(&w1_0[H64 + j]), __ldg(&b1_0[j])));
        float v1 = fmaf(a0, __ldg(&w1_1[j]), fmaf(a1, __ldg(&w1_1[H64 + j]), __ldg(&b1_1[j])));
        g_ht0[(size_t)j * E + e] = __float2half(fmaxf(v0, 0.0f));
        g_ht1[(size_t)j * E + e] = __float2half(fmaxf(v1, 0.0f));
        return;
    }
    if (b < nb_mlp + nb_prep) {
        // ---- pack B chunk64 tables (pair layout) ----
        int idx = (b - nb_mlp) * 256 + tid;          // < 66*2048
        int c = idx >> 11, rem = idx & 2047;
        int row = rem >> 7;
        int n   = (rem >> 1) & 63;
        int p   = rem & 1;
        int s = row >> 2, t = row & 3;
        int k0 = 2 * t + 8 * p;
        int word = row * 136 + n * 2 + p;

        if (c < 33) {       // layer 0
            float v0 = 0.f, v1 = 0.f;
            if (c < 32) {
                int k = 2 * c + (s >> 1);
                int i = (s & 1) * 16 + k0;
                v0 = w2_0[k * 2048 + i * H64 + n];
                v1 = w2_0[k * 2048 + (i + 1) * H64 + n];
            } else if (s < 2) {
                int i = s * 16 + k0;
                v0 = b2_0[i * H64 + n];
                v1 = b2_0[(i + 1) * H64 + n];
            }
            g_w2bh0[c * 2176 + word] = packf16(v0, v1);
        }
        {                   // layer 1
            int ih = (c >= 33) ? 1 : 0;
            int cc = c - 33 * ih;
            float v0 = 0.f, v1 = 0.f;
            if (cc < 32) {
                int k = 2 * cc + (s >> 1);
                int i = ih * 32 + (s & 1) * 16 + k0;
                v0 = w2_1[k * 4096 + i * H64 + n];
                v1 = w2_1[k * 4096 + (i + 1) * H64 + n];
            } else if (s < 2) {
                int i = ih * 32 + s * 16 + k0;
                v0 = b2_1[i * H64 + n];
                v1 = b2_1[(i + 1) * H64 + n];
            }
            g_w2bh1[c * 2176 + word] = packf16(v0, v1);
        }
        return;
    }
    // ---- root0: agg0 = x @ root_0 + bias_0 ; agg1 = 0 ----
    int idx = (b - nb_mlp - nb_prep) * 256 + tid;
    if (idx >= N * H64) return;
    int n = idx >> 6, t = idx & 63;
    float v = __ldg(&bias_0[t]);
    const float* xr = x + (size_t)n * 32;
    #pragma unroll
    for (int i = 0; i < 32; i++)
        v = fmaf(__ldg(&xr[i]), __ldg(&root_0[i * H64 + t]), v);
    g_agg0[idx] = v;
    g_agg1[idx] = 0.0f;
}

// ---------------- fused msg GEMM (mma.sync fp16) + scatter [+ root backfill]
// blocks [0, gridFuse): CTA = 128 edges x 64 outs, 4 warps (32x64 warp tile),
//   K-chunks of 64, triple-buffered cp.async for B + h(fp16).
// blocks >= gridFuse (layer 1 only): root1 term, grid-stride atomicAdd.
// PDL: layer 0 waits on prior kernel only before touching g_* (after x gather);
//      layer 1 waits at entry (x == agg0 from previous kernel).
template<int IN_C, bool RELU_IN>
__global__ void __launch_bounds__(128, 3)
fused_mma_kernel(const float* __restrict__ x, const int* __restrict__ ei, int E,
                 const __half* __restrict__ ht, const uint32_t* __restrict__ w2b,
                 float* __restrict__ agg,
                 const float* __restrict__ rootW, const float* __restrict__ rootB,
                 int N, int gridFuse, int rootBlocks)
{
    constexpr int NCHUNK = (IN_C == 32) ? 33 : 66;
    constexpr int XROW   = IN_C + 4;
    constexpr int B_OFF  = 0;                 // 3 x 8704
    constexpr int H_OFF  = 26112;             // 3 x 512 ([slot][kk][e], fp16)
    constexpr int X_OFF  = 27648;
    constexpr int DST_OFF = X_OFF + 128 * XROW * 4;

    int tid = threadIdx.x;

    if (RELU_IN) GDC_WAIT();     // x == agg0 written by previous kernel

    if (blockIdx.x >= (unsigned)gridFuse) {
        // ---- root backfill path (layer 1 only; no smem, no syncs) ----
        int stride = rootBlocks * 128;
        for (int idx = (blockIdx.x - gridFuse) * 128 + tid; idx < N * H64; idx += stride) {
            int n = idx >> 6, t = idx & 63;
            float v = __ldg(&rootB[t]);
            const float* xr = x + (size_t)n * H64;
            #pragma unroll
            for (int i = 0; i < H64; i++)
                v = fmaf(fmaxf(__ldg(&xr[i]), 0.0f), __ldg(&rootW[i * H64 + t]), v);
            atomicAdd(&agg[idx], v);
        }
        return;
    }

    extern __shared__ char smem[];
    float* x_s   = (float*)(smem + X_OFF);
    int*   dst_s = (int*)(smem + DST_OFF);
    uint32_t sbase = smem_u32(smem);

    int e0 = blockIdx.x * 128;

    // ---- gather x[src] tile (relu on read for layer 1) ----
    constexpr int XV = IN_C / 4;
    for (int q = tid; q < 128 * XV; q += 128) {
        int e = q / XV, cc = q % XV;
        int ge = e0 + e;
        int s = (ge < E) ? ei[ge] : 0;
        float4 v = *(const float4*)(x + (size_t)s * IN_C + cc * 4);
        if (RELU_IN) {
            v.x = fmaxf(v.x, 0.0f); v.y = fmaxf(v.y, 0.0f);
            v.z = fmaxf(v.z, 0.0f); v.w = fmaxf(v.w, 0.0f);
        }
        *(float4*)&x_s[e * XROW + cc * 4] = v;
    }
    dst_s[tid] = (e0 + tid < E) ? ei[E + e0 + tid] : -1;

    if (!RELU_IN) GDC_WAIT();    // layer 0: gather was independent of setup

    // ---- prefetch: B chunk (8704 B) + 2 h columns (512 B fp16) ----
    auto prefetch = [&](int c) {
        if (c < NCHUNK) {
            int slot = c % 3;
            uint32_t bs = sbase + B_OFF + slot * 8704;
            const char* g = (const char*)w2b + (size_t)c * 8704;
            #pragma unroll
            for (int o = 0; o < 8192; o += 2048)
                cp_async16(bs + o + tid * 16, g + o + tid * 16);
            if (tid < 32) cp_async16(bs + 8192 + tid * 16, g + 8192 + tid * 16);
            bool isBias = (IN_C == 32) ? (c == 32) : (c == 32 || c == 65);
            if (!isBias && tid < 32) {
                int cc = (IN_C == 32) ? c : ((c < 33) ? c : c - 33);
                int kk = tid >> 4, ln = tid & 15;
                cp_async16(sbase + H_OFF + slot * 512 + kk * 256 + ln * 16,
                           ht + (size_t)(2 * cc + kk) * E + e0 + ln * 8);
            }
        }
        CP_COMMIT();
    };
    prefetch(0);
    prefetch(1);
    __syncthreads();   // x_s / dst_s visible

    const int w    = tid >> 5;
    const int lane = tid & 31;
    const int gid  = lane >> 2;
    const int tig  = lane & 3;

    int rows[4];
    #pragma unroll
    for (int j = 0; j < 4; j++) rows[j] = w * 32 + j * 8 + gid;

    float xreg[4][8];
    auto load_xreg = [&](int ih) {
        #pragma unroll
        for (int r = 0; r < 4; r++)
            #pragma unroll
            for (int j = 0; j < 8; j++)
                xreg[r][j] = x_s[rows[r] * XROW + ih +
                                 (j >> 2) * 16 + 2 * tig + 8 * ((j >> 1) & 1) + (j & 1)];
    };
    load_xreg(0);

    float acc[2][8][4];
    #pragma unroll
    for (int mt = 0; mt < 2; mt++)
        #pragma unroll
        for (int q = 0; q < 8; q++)
            #pragma unroll
            for (int u = 0; u < 4; u++) acc[mt][q][u] = 0.0f;

    for (int c = 0; c < NCHUNK; c++) {
        if (IN_C == 64 && c == 33) load_xreg(32);
        CP_WAIT1();
        __syncthreads();
        prefetch(c + 2);

        int slot = c % 3;
        bool isBias = (IN_C == 32) ? (c == 32) : (c == 32 || c == 65);
        float hk[2][4];
        if (isBias) {
            #pragma unroll
            for (int j = 0; j < 4; j++) { hk[0][j] = 1.0f; hk[1][j] = 1.0f; }
        } else {
            const __half* hb = (const __half*)(smem + H_OFF + slot * 512);
            #pragma unroll
            for (int j = 0; j < 4; j++) {
                hk[0][j] = __half2float(hb[rows[j]]);
                hk[1][j] = __half2float(hb[128 + rows[j]]);
            }
        }

        uint32_t bbase = sbase + B_OFF + slot * 8704;
        #pragma unroll
        for (int s = 0; s < 4; s++) {
            int kk = s >> 1, jb = (s & 1) * 4;
            uint32_t a[2][4];
            #pragma unroll
            for (int mt = 0; mt < 2; mt++) {
                float h0 = hk[kk][mt * 2], h1 = hk[kk][mt * 2 + 1];
                const float* x0 = xreg[mt * 2];
                const float* x1 = xreg[mt * 2 + 1];
                a[mt][0] = packf16(h0 * x0[jb + 0], h0 * x0[jb + 1]);
                a[mt][1] = packf16(h1 * x1[jb + 0], h1 * x1[jb + 1]);
                a[mt][2] = packf16(h0 * x0[jb + 2], h0 * x0[jb + 3]);
                a[mt][3] = packf16(h1 * x1[jb + 2], h1 * x1[jb + 3]);
            }
            uint32_t brow = bbase + (uint32_t)(s * 4 + tig) * 544 + (uint32_t)gid * 8;
            #pragma unroll
            for (int q = 0; q < 8; q++) {
                uint32_t b0, b1;
                asm volatile("ld.shared.v2.b32 {%0, %1}, [%2];"
                             : "=r"(b0), "=r"(b1) : "r"(brow + q * 64));
                mma_f16(acc[0][q], a[0][0], a[0][1], a[0][2], a[0][3], b0, b1);
                mma_f16(acc[1][q], a[1][0], a[1][1], a[1][2], a[1][3], b0, b1);
            }
        }
    }

    // ---- scatter-add into agg[dst] ----
    #pragma unroll
    for (int mt = 0; mt < 2; mt++) {
        int d0 = dst_s[rows[mt * 2]];
        int d1 = dst_s[rows[mt * 2 + 1]];
        float* p0 = agg + (size_t)(d0 < 0 ? 0 : d0) * H64;
        float* p1 = agg + (size_t)(d1 < 0 ? 0 : d1) * H64;
        #pragma unroll
        for (int q = 0; q < 8; q++) {
            int n = q * 8 + tig * 2;
            if (d0 >= 0) {
                atomicAdd(p0 + n,     acc[mt][q][0]);
                atomicAdd(p0 + n + 1, acc[mt][q][1]);
            }
            if (d1 >= 0) {
                atomicAdd(p1 + n,     acc[mt][q][2]);
                atomicAdd(p1 + n + 1, acc[mt][q][3]);
            }
        }
    }
}

// ---------------- relu out (vectorized, PDL wait) ---------------------------
__global__ void __launch_bounds__(256)
relu_out_kernel(const float4* __restrict__ in, float4* __restrict__ out, int n4)
{
    GDC_WAIT();
    int stride = gridDim.x * blockDim.x;
    for (int i = blockIdx.x * blockDim.x + threadIdx.x; i < n4; i += stride) {
        float4 v = in[i];
        v.x = fmaxf(v.x, 0.0f); v.y = fmaxf(v.y, 0.0f);
        v.z = fmaxf(v.z, 0.0f); v.w = fmaxf(v.w, 0.0f);
        out[i] = v;
    }
}

// ---------------- launch -----------------------------------------------------
extern "C" void kernel_launch(void* const* d_in, const int* in_sizes, int n_in,
                              void* d_out, int out_size)
{
    const float* x      = (const float*)d_in[0];
    const int*   ei     = (const int*)  d_in[1];
    const float* ea     = (const float*)d_in[2];
    const float* w1_0   = (const float*)d_in[3];
    const float* b1_0   = (const float*)d_in[4];
    const float* w2_0   = (const float*)d_in[5];
    const float* b2_0   = (const float*)d_in[6];
    const float* root_0 = (const float*)d_in[7];
    const float* bias_0 = (const float*)d_in[8];
    const float* w1_1   = (const float*)d_in[9];
    const float* b1_1   = (const float*)d_in[10];
    const float* w2_1   = (const float*)d_in[11];
    const float* b2_1   = (const float*)d_in[12];
    const float* root_1 = (const float*)d_in[13];
    const float* bias_1 = (const float*)d_in[14];

    const int N = in_sizes[0] / 32;   // 20000
    const int E = in_sizes[1] / 2;    // 50000

    void* p;
    cudaGetSymbolAddress(&p, g_ht0);   __half* ht0 = (__half*)p;
    cudaGetSymbolAddress(&p, g_ht1);   __half* ht1 = (__half*)p;
    cudaGetSymbolAddress(&p, g_w2bh0); uint32_t* w2b0 = (uint32_t*)p;
    cudaGetSymbolAddress(&p, g_w2bh1); uint32_t* w2b1 = (uint32_t*)p;
    cudaGetSymbolAddress(&p, g_agg0);  float* agg0 = (float*)p;
    cudaGetSymbolAddress(&p, g_agg1);  float* agg1 = (float*)p;

    const int smem0 = 27648 + 128 * 36 * 4 + 512;   // 46592
    const int smem1 = 27648 + 128 * 68 * 4 + 512;   // 62976
    cudaFuncSetAttribute(fused_mma_kernel<32, false>,
                         cudaFuncAttributeMaxDynamicSharedMemorySize, smem0);
    cudaFuncSetAttribute(fused_mma_kernel<64, true>,
                         cudaFuncAttributeMaxDynamicSharedMemorySize, smem1);

    // ---- launch A: setup mega-kernel (plain launch) ----
    const int ebpj    = (E + 255) / 256;
    const int nb_mlp  = ebpj * H64;
    const int nb_prep = (66 * 2048) / 256;          // 528
    const int nb_root = (N * H64 + 255) / 256;
    setup_kernel<<<nb_mlp + nb_prep + nb_root, 256>>>(
        ea, w1_0, b1_0, w1_1, b1_1, w2_0, b2_0, w2_1, b2_1,
        x, root_0, bias_0, E, N, ebpj, nb_mlp, nb_prep);

    const int grid_fuse = (E + 127) / 128;
    const int ROOT_BLKS = 592;

    cudaLaunchAttribute pdl[1];
    pdl[0].id = cudaLaunchAttributeProgrammaticStreamSerialization;
    pdl[0].val.programmaticStreamSerializationAllowed = 1;

    // ---- launch B: fused layer 0 (PDL after setup) ----
    {
        cudaLaunchConfig_t cfg{};
        cfg.gridDim = dim3(grid_fuse);
        cfg.blockDim = dim3(128);
        cfg.dynamicSmemBytes = smem0;
        cfg.stream = 0;
        cfg.attrs = pdl;
        cfg.numAttrs = 1;
        const float* nW = nullptr; const float* nB = nullptr;
        cudaLaunchKernelEx(&cfg, fused_mma_kernel<32, false>,
                           x, ei, E, (const __half*)ht0, (const uint32_t*)w2b0,
                           agg0, nW, nB, N, grid_fuse, 0);
    }

    // ---- launch C: fused layer 1 + root1 backfill (PDL after B) ----
    {
        cudaLaunchConfig_t cfg{};
        cfg.gridDim = dim3(grid_fuse + ROOT_BLKS);
        cfg.blockDim = dim3(128);
        cfg.dynamicSmemBytes = smem1;
        cfg.stream = 0;
        cfg.attrs = pdl;
        cfg.numAttrs = 1;
        cudaLaunchKernelEx(&cfg, fused_mma_kernel<64, true>,
                           (const float*)agg0, ei, E, (const __half*)ht1,
                           (const uint32_t*)w2b1, agg1,
                           root_1, bias_1, N, grid_fuse, ROOT_BLKS);
    }

    // ---- launch D: relu out (PDL after C) ----
    {
        cudaLaunchConfig_t cfg{};
        cfg.gridDim = dim3(640);
        cfg.blockDim = dim3(256);
        cfg.dynamicSmemBytes = 0;
        cfg.stream = 0;
        cfg.attrs = pdl;
        cfg.numAttrs = 1;
        cudaLaunchKernelEx(&cfg, relu_out_kernel,
                           (const float4*)agg1, (float4*)d_out, (N * H64) / 4);
    }
}